// round 6
// baseline (speedup 1.0000x reference)
#include <cuda_runtime.h>
#include <cstdint>

// ============================================================================
// GRU_Att_Layer R6: persistent kernel, weight-stationary SMEM.
//  - gh CTA-local (gate-triple w_hh rows) -> no g_gh global round trip
//  - merged, load-balanced A1+A2 dot phase (128 thr A1 / 192 thr A2)
//  - float4 burst staging; x(t+1) prefetch overlaps epilogue+barrier
//  - packed fma.rn.f32x2 4x4 register tiles, k-split + SMEM reduce
// B=128,S=1024,I=256,H=256. 128 CTAs: g=blockIdx&15 rows, p=blockIdx>>4
// batch-group (16 batches). 16-CTA batch-group barriers, 2 per step.
// ============================================================================

#define S_LEN 1024
#define NBLK  128
#define NTHR  384

#define ZSTR  20
#define W1STR 20
#define W2STR 52
#define WCSTR 52
#define GHSTR 20
#define RT1   132    // A1 partials: 16 vals * 8 ks + 4 pad
#define RT2   68     // A2 partials: 16 vals * 4 ks + 4 pad
#define RTC   132    // C  partials: 16 vals * 8 ks + 4 pad

// SMEM layout (float offsets)
#define OFF_W1  0                       // [512][20] W_att^T (16 rows)
#define OFF_W2  (OFF_W1 + 512*W1STR)    // 10240: [256][52] w_hh^T gate-triples
#define OFF_WC  (OFF_W2 + 256*W2STR)    // 23552: [256][52] w_ih^T gate-triples
#define OFF_Z   (OFF_WC + 256*WCSTR)    // 36864: [512][20] zT = [x|xg ; h]^T
#define OFF_RED (OFF_Z  + 512*ZSTR)     // 47104
#define OFF_RA1 OFF_RED                 // 16*132 = 2112
#define OFF_RA2 (OFF_RED + 16*RT1)      // 49216: 48*68 = 3264 (ends 52480)
#define OFF_RC  OFF_RED                 // 48*132 = 6336 (overlays RA1/RA2)
#define OFF_GH  (OFF_RED + 48*RTC)      // 53440: [48][20]
#define OFF_BA  (OFF_GH + 48*GHSTR)     // 54400
#define OFF_BHH (OFF_BA + 16)
#define OFF_BIH (OFF_BHH + 48)
#define SMEM_FLOATS (OFF_BIH + 48)      // 54512
#define SMEM_BYTES  (SMEM_FLOATS * 4)   // 218048 B < 227 KB opt-in

// ---------------- scratch (device globals; allocation forbidden) -----------
__device__ __align__(16) float g_h [128 * 256];
__device__ __align__(16) float g_xg[128 * 256];
__device__ unsigned g_cnt[8 * 32];
__device__ unsigned g_gen[8 * 32];

// ---------------- 16-CTA batch-group barrier --------------------------------
__device__ __forceinline__ void pbar(int grp) {
    __syncthreads();
    if (threadIdx.x == 0) {
        volatile unsigned* cnt = &g_cnt[grp * 32];
        volatile unsigned* gen = &g_gen[grp * 32];
        __threadfence();
        unsigned gv = *gen;
        if (atomicAdd((unsigned*)cnt, 1u) == 15u) {
            *cnt = 0u;
            __threadfence();
            *gen = gv + 1u;
        } else {
            while (*gen == gv) { }
        }
        __threadfence();
    }
    __syncthreads();
}

__device__ __forceinline__ float sigmoidf_(float x) {
    return 1.0f / (1.0f + __expf(-x));
}
__device__ __forceinline__ uint32_t sm_u32(const void* p) {
    uint32_t a;
    asm("{ .reg .u64 t; cvta.to.shared.u64 t, %1; cvt.u32.u64 %0, t; }"
        : "=r"(a) : "l"(p));
    return a;
}
__device__ __forceinline__ float2 unpk(unsigned long long v) {
    uint32_t lo, hi;
    asm("mov.b64 {%0,%1}, %2;" : "=r"(lo), "=r"(hi) : "l"(v));
    return make_float2(__uint_as_float(lo), __uint_as_float(hi));
}
__device__ __forceinline__ unsigned long long dup2(float w) {
    unsigned long long d; uint32_t u = __float_as_uint(w);
    asm("mov.b64 %0, {%1,%1};" : "=l"(d) : "r"(u));
    return d;
}
#define FMA2(acc, a, b) \
    asm("fma.rn.f32x2 %0, %1, %2, %0;" : "+l"(acc) : "l"(a), "l"(b))

// NITER-iteration 4-row x 4-batch outer-product dot (one k per iter).
// acc[rl*2+bp] = packed batches (2bp, 2bp+1) for local row rl.
template <int NITER>
__device__ __forceinline__ void dot_4r(uint32_t za, uint32_t wa,
                                       int zstep, int wstep,
                                       unsigned long long acc[8]) {
#pragma unroll 8
    for (int i = 0; i < NITER; ++i) {
        unsigned long long z01, z23;
        asm volatile("ld.shared.v2.b64 {%0,%1}, [%2];"
                     : "=l"(z01), "=l"(z23) : "r"(za));
        float w0, w1, w2, w3;
        asm volatile("ld.shared.v4.f32 {%0,%1,%2,%3}, [%4];"
                     : "=f"(w0), "=f"(w1), "=f"(w2), "=f"(w3) : "r"(wa));
        unsigned long long d;
        d = dup2(w0); FMA2(acc[0], d, z01); FMA2(acc[1], d, z23);
        d = dup2(w1); FMA2(acc[2], d, z01); FMA2(acc[3], d, z23);
        d = dup2(w2); FMA2(acc[4], d, z01); FMA2(acc[5], d, z23);
        d = dup2(w3); FMA2(acc[6], d, z01); FMA2(acc[7], d, z23);
        za += zstep; wa += wstep;
    }
}

// scatter 8 f32x2 accs into partial buffer: rb[(rl*4 + bl)*STRIDE]
template <int STRIDE>
__device__ __forceinline__ void store_part(float* rb, unsigned long long acc[8]) {
#pragma unroll
    for (int rl = 0; rl < 4; ++rl)
#pragma unroll
        for (int bp = 0; bp < 2; ++bp) {
            float2 v = unpk(acc[rl * 2 + bp]);
            rb[(rl * 4 + bp * 2    ) * STRIDE] = v.x;
            rb[(rl * 4 + bp * 2 + 1) * STRIDE] = v.y;
        }
}

__global__ void __launch_bounds__(NTHR, 1)
gru_att_persistent(const float* __restrict__ x,      // [B,S,I]
                   const float* __restrict__ hid,    // [B,H]
                   const float* __restrict__ W_att,  // [256,512]
                   const float* __restrict__ b_att,  // [256]
                   const float* __restrict__ w_ih,   // [768,256]
                   const float* __restrict__ b_ih,   // [768]
                   const float* __restrict__ w_hh,   // [768,256]
                   const float* __restrict__ b_hh,   // [768]
                   float* __restrict__ out)          // [B,S,H]
{
    extern __shared__ float smf[];
    const int tid = threadIdx.x;
    const int g   = blockIdx.x & 15;   // row group
    const int p   = blockIdx.x >> 4;   // batch group
    const uint32_t smb = sm_u32(smf);

    // ---- stage weights (once): all transposed, gate-triple row sets ----
    for (int idx = tid; idx < 512 * 16; idx += NTHR) {       // wa1T[k][rr]
        int k = idx >> 4, rr = idx & 15;
        smf[OFF_W1 + k * W1STR + rr] = W_att[(g * 16 + rr) * 512 + k];
    }
    for (int idx = tid; idx < 256 * 48; idx += NTHR) {       // wa2T[k][gate*16+jj]
        int k = idx / 48, rl = idx % 48;
        int gate = rl >> 4, jj = rl & 15;
        smf[OFF_W2 + k * W2STR + rl] = w_hh[(gate * 256 + g * 16 + jj) * 256 + k];
    }
    for (int idx = tid; idx < 256 * 48; idx += NTHR) {       // wcT[k][gate*16+jj]
        int k = idx / 48, rl = idx % 48;
        int gate = rl >> 4, jj = rl & 15;
        smf[OFF_WC + k * WCSTR + rl] = w_ih[(gate * 256 + g * 16 + jj) * 256 + k];
    }
    if (tid < 16) smf[OFF_BA + tid] = b_att[g * 16 + tid];
    if (tid < 48) {
        int gate = tid >> 4, jj = tid & 15;
        smf[OFF_BHH + tid] = b_hh[gate * 256 + g * 16 + jj];
        smf[OFF_BIH + tid] = b_ih[gate * 256 + g * 16 + jj];
    }

    // ---- init hidden state (one writer block per batch group) ----
    if (g == 0) {
        for (int idx = tid; idx < 16 * 256; idx += NTHR) {
            int bb = idx >> 8, k = idx & 255;
            g_h[(p * 16 + bb) * 256 + k] = hid[(p * 16 + bb) * 256 + k];
        }
    }

    // ---- prefetch x(t=0) into zT x-region (float4 bursts) ----
    for (int idx = tid; idx < 16 * 64; idx += NTHR) {
        int bb = idx >> 6, q = (idx & 63) << 2;
        float4 v = *(const float4*)&x[((p * 16 + bb) * S_LEN + 0) * 256 + q];
        int base = OFF_Z + q * ZSTR + bb;
        smf[base] = v.x; smf[base + ZSTR] = v.y;
        smf[base + 2 * ZSTR] = v.z; smf[base + 3 * ZSTR] = v.w;
    }

    // ---- per-thread dot-tile constants ----
    // A1: tid < 128. 16 tiles (4bq x 4rq) x ksplit 8. 1024 MACs/thread.
    const int a1_ks = tid & 7, a1_tile = tid >> 3;
    const int a1_bq = a1_tile >> 2, a1_rq = a1_tile & 3;
    const uint32_t a1_z0 = smb + (OFF_Z + a1_ks * ZSTR + a1_bq * 4) * 4;
    const uint32_t a1_w0 = smb + (OFF_W1 + a1_ks * W1STR + a1_rq * 4) * 4;
    // A2: tid in [128,320). 48 tiles (4bq x 12rq) x ksplit 4. 1024 MACs/thread.
    const int a2i = tid - 128;
    const int a2_ks = a2i & 3, a2_tile = a2i >> 2;
    const int a2_bq = a2_tile / 12, a2_rq = a2_tile % 12;
    const uint32_t a2_z0 = smb + (OFF_Z + (256 + a2_ks) * ZSTR + a2_bq * 4) * 4;
    const uint32_t a2_w0 = smb + (OFF_W2 + a2_ks * W2STR + a2_rq * 4) * 4;
    // C: all 384. 48 tiles x ksplit 8. 512 MACs/thread.
    const int c_ks = tid & 7, c_tile = tid >> 3;
    const int c_bq = c_tile / 12, c_rq = c_tile % 12;
    const uint32_t c_z0 = smb + (OFF_Z + c_ks * ZSTR + c_bq * 4) * 4;
    const uint32_t c_w0 = smb + (OFF_WC + c_ks * WCSTR + c_rq * 4) * 4;

    pbar(p);   // h initialized, x staged

    for (int t = 0; t < S_LEN; ++t) {
        // ---- stage h -> zT[256+k][bb] (float4 bursts) ----
        for (int idx = tid; idx < 16 * 64; idx += NTHR) {
            int bb = idx >> 6, q = (idx & 63) << 2;
            float4 v = *(const float4*)&g_h[(p * 16 + bb) * 256 + q];
            int base = OFF_Z + (256 + q) * ZSTR + bb;
            smf[base] = v.x; smf[base + ZSTR] = v.y;
            smf[base + 2 * ZSTR] = v.z; smf[base + 3 * ZSTR] = v.w;
        }
        __syncthreads();

        // ========== merged dot: A1 (warps 0-3) + A2 (warps 4-9) ==========
        if (tid < 128) {
            unsigned long long acc[8] = {0,0,0,0,0,0,0,0};
            dot_4r<64>(a1_z0, a1_w0, 8 * ZSTR * 4, 8 * W1STR * 4, acc);
            store_part<8>(smf + OFF_RA1 + a1_tile * RT1 + a1_ks, acc);
        } else if (tid < 320) {
            unsigned long long acc[8] = {0,0,0,0,0,0,0,0};
            dot_4r<64>(a2_z0, a2_w0, 4 * ZSTR * 4, 4 * W2STR * 4, acc);
            store_part<4>(smf + OFF_RA2 + a2_tile * RT2 + a2_ks, acc);
        }
        __syncthreads();

        // ---- A2 reduce (all 384 threads, 2 outputs each) -> gh in SMEM ----
#pragma unroll
        for (int rep = 0; rep < 2; ++rep) {
            int o = tid + rep * NTHR;          // o = b*48 + r
            int b = o / 48, r = o % 48;
            const float* rp = smf + OFF_RA2
                + ((b >> 2) * 12 + (r >> 2)) * RT2
                + ((r & 3) * 4 + (b & 3)) * 4;
            float4 q0 = *(const float4*)rp;
            smf[OFF_GH + r * GHSTR + b] =
                ((q0.x + q0.y) + (q0.z + q0.w)) + smf[OFF_BHH + r];
        }
        // ---- A1 reduce (tid<256) -> xg -> g_xg ----
        if (tid < 256) {
            int rr = tid & 15, bb = tid >> 4;
            const float* rp = smf + OFF_RA1
                + ((bb >> 2) * 4 + (rr >> 2)) * RT1
                + ((rr & 3) * 4 + (bb & 3)) * 8;
            float4 q0 = *(const float4*)rp;
            float4 q1 = *(const float4*)(rp + 4);
            float s = ((q0.x+q0.y)+(q0.z+q0.w)) + ((q1.x+q1.y)+(q1.z+q1.w))
                    + smf[OFF_BA + rr];
            float a  = sigmoidf_(s);
            float xv = smf[OFF_Z + (g * 16 + rr) * ZSTR + bb];
            g_xg[(p * 16 + bb) * 256 + g * 16 + rr] = xv * a;
        }

        pbar(p);   // xg published within batch group (gh is local)

        // ---- stage xg -> zT x-region (float4 bursts) ----
        for (int idx = tid; idx < 16 * 64; idx += NTHR) {
            int bb = idx >> 6, q = (idx & 63) << 2;
            float4 v = *(const float4*)&g_xg[(p * 16 + bb) * 256 + q];
            int base = OFF_Z + q * ZSTR + bb;
            smf[base] = v.x; smf[base + ZSTR] = v.y;
            smf[base + 2 * ZSTR] = v.z; smf[base + 3 * ZSTR] = v.w;
        }
        __syncthreads();

        // ========== C: w_ih gate-triples over xg, K=256 ==========
        {
            unsigned long long acc[8] = {0,0,0,0,0,0,0,0};
            dot_4r<32>(c_z0, c_w0, 8 * ZSTR * 4, 8 * WCSTR * 4, acc);
            store_part<8>(smf + OFF_RC + c_tile * RTC + c_ks, acc);
        }
        __syncthreads();

        // ---- C reduce + gate math (tid<256); everything SMEM-local ----
        if (tid < 256) {
            int jj = tid & 15, bb = tid >> 4;
            int b  = p * 16 + bb;
            int j  = g * 16 + jj;
            float hp  = smf[OFF_Z + (256 + j) * ZSTR + bb];
            float ghr = smf[OFF_GH + (      jj) * GHSTR + bb];
            float ghz = smf[OFF_GH + (16 + jj) * GHSTR + bb];
            float ghn = smf[OFF_GH + (32 + jj) * GHSTR + bb];
            float gi[3];
#pragma unroll
            for (int gate = 0; gate < 3; ++gate) {
                int r = gate * 16 + jj;
                const float* rp = smf + OFF_RC
                    + ((bb >> 2) * 12 + (r >> 2)) * RTC
                    + ((r & 3) * 4 + (bb & 3)) * 8;
                float4 q0 = *(const float4*)rp;
                float4 q1 = *(const float4*)(rp + 4);
                gi[gate] = ((q0.x+q0.y)+(q0.z+q0.w)) + ((q1.x+q1.y)+(q1.z+q1.w))
                         + smf[OFF_BIH + r];
            }
            float r_ = sigmoidf_(gi[0] + ghr);
            float z_ = sigmoidf_(gi[1] + ghz);
            float n_ = tanhf(gi[2] + r_ * ghn);
            float hn = (1.0f - z_) * n_ + z_ * hp;
            g_h[b * 256 + j] = hn;
            out[(b * S_LEN + t) * 256 + j] = hn;
        }

        // ---- prefetch x(t+1) -> zT x-region (overlaps epilogue + barrier) ----
        if (t + 1 < S_LEN) {
            for (int idx = tid; idx < 16 * 64; idx += NTHR) {
                int bb = idx >> 6, q = (idx & 63) << 2;
                float4 v = *(const float4*)
                    &x[((p * 16 + bb) * S_LEN + (t + 1)) * 256 + q];
                int base = OFF_Z + q * ZSTR + bb;
                smf[base] = v.x; smf[base + ZSTR] = v.y;
                smf[base + 2 * ZSTR] = v.z; smf[base + 3 * ZSTR] = v.w;
            }
        }

        pbar(p);   // h_new published within batch group
    }
}

extern "C" void kernel_launch(void* const* d_in, const int* in_sizes, int n_in,
                              void* d_out, int out_size) {
    const float* x     = (const float*)d_in[0];
    const float* hid   = (const float*)d_in[1];
    const float* W_att = (const float*)d_in[2];
    const float* b_att = (const float*)d_in[3];
    const float* w_ih  = (const float*)d_in[4];
    const float* b_ih  = (const float*)d_in[5];
    const float* w_hh  = (const float*)d_in[6];
    const float* b_hh  = (const float*)d_in[7];
    float* out = (float*)d_out;

    cudaFuncSetAttribute(gru_att_persistent,
                         cudaFuncAttributeMaxDynamicSharedMemorySize, SMEM_BYTES);

    gru_att_persistent<<<NBLK, NTHR, SMEM_BYTES>>>(
        x, hid, W_att, b_att, w_ih, b_ih, w_hh, b_hh, out);
}

// round 7
// speedup vs baseline: 1.1675x; 1.1675x over previous
#include <cuda_runtime.h>
#include <cstdint>

// ============================================================================
// GRU_Att_Layer R7: persistent kernel, weight-stationary SMEM.
//  - 8row x 4batch dot tiles, lanes=(ks,bq): w-operand LDS is 1-wavefront
//    (4-lane broadcast), z is 4 balanced wavefronts -> 0.75 B/MAC crossbar
//  - in-warp shfl-tree reduction over ks (no SMEM partials for A2)
//  - conflict-free transposed staging (lane == batch)
//  - flag-array group barrier (launch-safe epoch snapshot)
// B=128,S=1024,I=256,H=256. 128 CTAs: g=blockIdx&15 rows, p=blockIdx>>4
// (16 batches). 384 threads.
// ============================================================================

#define S_LEN 1024
#define NBLK  128
#define NTHR  384

#define ZSTR  20
#define W1STR 20
#define W2STR 52
#define WCSTR 52
#define GHSTR 20
#define PBS   18     // partial row stride (16 batches + 2 pad)

// SMEM layout (float offsets)
#define OFF_W1   0                        // [512][20]  W_att^T (16 rows)
#define OFF_W2   (OFF_W1 + 512*W1STR)     // 10240 [256][52] w_hh^T gate-triples
#define OFF_WC   (OFF_W2 + 256*W2STR)     // 23552 [256][52] w_ih^T gate-triples
#define OFF_Z    (OFF_WC + 256*WCSTR)     // 36864 [512][20] zT=[x|xg ; h]^T
#define OFF_GH   (OFF_Z  + 512*ZSTR)      // 47104 [48][20]
#define OFF_PB1  (OFF_GH + 48*GHSTR)      // 48064 [2][16][18]
#define OFF_PBC  (OFF_PB1 + 2*16*PBS)     // 48640 [2][48][18]
#define OFF_BA   (OFF_PBC + 2*48*PBS)     // 50368
#define OFF_BHH  (OFF_BA + 16)
#define OFF_BIH  (OFF_BHH + 48)
#define OFF_BASE (OFF_BIH + 48)           // 50480: 16 barrier bases (as uint)
#define SMEM_FLOATS (OFF_BASE + 16)       // 50496
#define SMEM_BYTES  (SMEM_FLOATS * 4)     // 201984 B

// ---------------- scratch (device globals; allocation forbidden) -----------
__device__ __align__(16) float g_h [128 * 256];
__device__ __align__(16) float g_xg[128 * 256];
__device__ unsigned g_flag[NBLK * 32];   // per-CTA epoch, own sector

// ---------------- barrier: per-CTA epoch flags, 16 pollers ------------------
__device__ __forceinline__ void pbar(const unsigned* base_sm, int p, int g,
                                     unsigned n) {
    __syncthreads();                       // all CTA work done
    if (threadIdx.x == 0) {
        __threadfence();                   // publish this CTA's stores
        *(volatile unsigned*)&g_flag[blockIdx.x * 32] = base_sm[g] + n;
    }
    if (threadIdx.x < 16) {
        volatile unsigned* f = &g_flag[(p * 16 + threadIdx.x) * 32];
        unsigned tgt = base_sm[threadIdx.x] + n;
        while ((int)(*f - tgt) < 0) { }
        __threadfence();                   // acquire
    }
    __syncthreads();
}

__device__ __forceinline__ float sigmoidf_(float x) {
    return 1.0f / (1.0f + __expf(-x));
}
__device__ __forceinline__ uint32_t sm_u32(const void* ptr) {
    uint32_t a;
    asm("{ .reg .u64 t; cvta.to.shared.u64 t, %1; cvt.u32.u64 %0, t; }"
        : "=r"(a) : "l"(ptr));
    return a;
}
__device__ __forceinline__ float2 unpk(unsigned long long v) {
    uint32_t lo, hi;
    asm("mov.b64 {%0,%1}, %2;" : "=r"(lo), "=r"(hi) : "l"(v));
    return make_float2(__uint_as_float(lo), __uint_as_float(hi));
}
__device__ __forceinline__ unsigned long long dup2(float w) {
    unsigned long long d; uint32_t u = __float_as_uint(w);
    asm("mov.b64 %0, {%1,%1};" : "=l"(d) : "r"(u));
    return d;
}
#define FMA2(acc, a, b) \
    asm("fma.rn.f32x2 %0, %1, %2, %0;" : "+l"(acc) : "l"(a), "l"(b))
#define ADD2(d, s) \
    asm("add.rn.f32x2 %0, %0, %1;" : "+l"(d) : "l"(s))

// 8-row x 4-batch dot. lane=(ks=lane&7, bq=lane>>3). One k per iter per lane.
// acc[r*2+bp]: row r (local), packed batches (bq*4+2bp, +1).
template <int NITER>
__device__ __forceinline__ void dot8r(uint32_t za, uint32_t wa,
                                      int zstep, int wstep,
                                      unsigned long long acc[16]) {
#pragma unroll 4
    for (int i = 0; i < NITER; ++i) {
        unsigned long long z01, z23;
        asm volatile("ld.shared.v2.b64 {%0,%1}, [%2];"
                     : "=l"(z01), "=l"(z23) : "r"(za));
        float w0, w1, w2, w3, w4, w5, w6, w7;
        asm volatile("ld.shared.v4.f32 {%0,%1,%2,%3}, [%4];"
                     : "=f"(w0), "=f"(w1), "=f"(w2), "=f"(w3) : "r"(wa));
        asm volatile("ld.shared.v4.f32 {%0,%1,%2,%3}, [%4];"
                     : "=f"(w4), "=f"(w5), "=f"(w6), "=f"(w7) : "r"(wa + 16));
        unsigned long long d;
        d = dup2(w0); FMA2(acc[0],  d, z01); FMA2(acc[1],  d, z23);
        d = dup2(w1); FMA2(acc[2],  d, z01); FMA2(acc[3],  d, z23);
        d = dup2(w2); FMA2(acc[4],  d, z01); FMA2(acc[5],  d, z23);
        d = dup2(w3); FMA2(acc[6],  d, z01); FMA2(acc[7],  d, z23);
        d = dup2(w4); FMA2(acc[8],  d, z01); FMA2(acc[9],  d, z23);
        d = dup2(w5); FMA2(acc[10], d, z01); FMA2(acc[11], d, z23);
        d = dup2(w6); FMA2(acc[12], d, z01); FMA2(acc[13], d, z23);
        d = dup2(w7); FMA2(acc[14], d, z01); FMA2(acc[15], d, z23);
        za += zstep; wa += wstep;
    }
}

// shfl tree-reduce over ks (8 lanes). After: acc[0] = batches(bq*4+0,1),
// acc[1] = batches(bq*4+2,3) for local row == ks, summed over all 8 ks.
__device__ __forceinline__ void kreduce8(unsigned long long acc[16], int ks) {
    const bool h4 = (ks & 4) != 0;
#pragma unroll
    for (int r = 0; r < 4; ++r)
#pragma unroll
        for (int bp = 0; bp < 2; ++bp) {
            unsigned long long snd = h4 ? acc[r*2+bp] : acc[(r+4)*2+bp];
            unsigned long long kpt = h4 ? acc[(r+4)*2+bp] : acc[r*2+bp];
            unsigned long long rcv = __shfl_xor_sync(0xffffffffu, snd, 4);
            ADD2(kpt, rcv);
            acc[r*2+bp] = kpt;
        }
    const bool h2 = (ks & 2) != 0;
#pragma unroll
    for (int r = 0; r < 2; ++r)
#pragma unroll
        for (int bp = 0; bp < 2; ++bp) {
            unsigned long long snd = h2 ? acc[r*2+bp] : acc[(r+2)*2+bp];
            unsigned long long kpt = h2 ? acc[(r+2)*2+bp] : acc[r*2+bp];
            unsigned long long rcv = __shfl_xor_sync(0xffffffffu, snd, 2);
            ADD2(kpt, rcv);
            acc[r*2+bp] = kpt;
        }
    const bool h1 = (ks & 1) != 0;
#pragma unroll
    for (int bp = 0; bp < 2; ++bp) {
        unsigned long long snd = h1 ? acc[bp] : acc[2+bp];
        unsigned long long kpt = h1 ? acc[2+bp] : acc[bp];
        unsigned long long rcv = __shfl_xor_sync(0xffffffffu, snd, 1);
        ADD2(kpt, rcv);
        acc[bp] = kpt;
    }
}

__global__ void __launch_bounds__(NTHR, 1)
gru_att_persistent(const float* __restrict__ x,      // [B,S,I]
                   const float* __restrict__ hid,    // [B,H]
                   const float* __restrict__ W_att,  // [256,512]
                   const float* __restrict__ b_att,  // [256]
                   const float* __restrict__ w_ih,   // [768,256]
                   const float* __restrict__ b_ih,   // [768]
                   const float* __restrict__ w_hh,   // [768,256]
                   const float* __restrict__ b_hh,   // [768]
                   float* __restrict__ out)          // [B,S,H]
{
    extern __shared__ float smf[];
    const int tid  = threadIdx.x;
    const int g    = blockIdx.x & 15;   // row group
    const int p    = blockIdx.x >> 4;   // batch group
    const int wid  = tid >> 5;
    const int lane = tid & 31;
    const int ks   = lane & 7;
    const int bq   = lane >> 3;
    const uint32_t smb = sm_u32(smf);
    unsigned* base_sm = (unsigned*)(smf + OFF_BASE);

    // ---- barrier base snapshot (prev-launch values are stable now) ----
    if (tid < 16) base_sm[tid] = g_flag[(p * 16 + tid) * 32];

    // ---- stage weights (transposed, gate-triple row sets) ----
    for (int idx = tid; idx < 512 * 16; idx += NTHR) {
        int k = idx >> 4, rr = idx & 15;
        smf[OFF_W1 + k * W1STR + rr] = W_att[(g * 16 + rr) * 512 + k];
    }
    for (int idx = tid; idx < 256 * 48; idx += NTHR) {
        int k = idx / 48, rl = idx % 48;
        int gate = rl >> 4, jj = rl & 15;
        smf[OFF_W2 + k * W2STR + rl] = w_hh[(gate * 256 + g * 16 + jj) * 256 + k];
    }
    for (int idx = tid; idx < 256 * 48; idx += NTHR) {
        int k = idx / 48, rl = idx % 48;
        int gate = rl >> 4, jj = rl & 15;
        smf[OFF_WC + k * WCSTR + rl] = w_ih[(gate * 256 + g * 16 + jj) * 256 + k];
    }
    if (tid < 16) smf[OFF_BA + tid] = b_att[g * 16 + tid];
    if (tid < 48) {
        int gate = tid >> 4, jj = tid & 15;
        smf[OFF_BHH + tid] = b_hh[gate * 256 + g * 16 + jj];
        smf[OFF_BIH + tid] = b_ih[gate * 256 + g * 16 + jj];
    }

    // ---- init hidden state (one writer block per batch group) ----
    if (g == 0) {
        for (int idx = tid; idx < 16 * 256; idx += NTHR) {
            int bb = idx >> 8, k = idx & 255;
            g_h[(p * 16 + bb) * 256 + k] = hid[(p * 16 + bb) * 256 + k];
        }
    }

    // ---- prefetch x(t=0) -> zT x-region (conflict-free: lane==batch) ----
    for (int idx = tid; idx < 1024; idx += NTHR) {
        int bb = idx & 15, q4 = idx >> 4;
        float4 v = *(const float4*)&x[((p * 16 + bb) * S_LEN + 0) * 256 + q4 * 4];
        int base = OFF_Z + (q4 * 4) * ZSTR + bb;
        smf[base] = v.x; smf[base + ZSTR] = v.y;
        smf[base + 2 * ZSTR] = v.z; smf[base + 3 * ZSTR] = v.w;
    }

    unsigned barn = 1;
    pbar(base_sm, p, g, barn);   // h initialized, weights+x staged

    for (int t = 0; t < S_LEN; ++t) {
        // ---- stage h -> zT[256+k][bb] (1 wf per STS) ----
        for (int idx = tid; idx < 1024; idx += NTHR) {
            int bb = idx & 15, q4 = idx >> 4;
            float4 v = *(const float4*)&g_h[(p * 16 + bb) * 256 + q4 * 4];
            int base = OFF_Z + (256 + q4 * 4) * ZSTR + bb;
            smf[base] = v.x; smf[base + ZSTR] = v.y;
            smf[base + 2 * ZSTR] = v.z; smf[base + 3 * ZSTR] = v.w;
        }
        __syncthreads();

        // ===== dot1: warps 0-3 A1 (2 oct x 2 kh), warps 4-9 A2 (6 oct) =====
        if (wid < 4) {
            const int oct = wid >> 1, kh = wid & 1;
            unsigned long long acc[16] = {0,0,0,0,0,0,0,0,0,0,0,0,0,0,0,0};
            uint32_t za = smb + (OFF_Z  + (kh * 256 + ks) * ZSTR  + bq * 4) * 4;
            uint32_t wa = smb + (OFF_W1 + (kh * 256 + ks) * W1STR + oct * 8) * 4;
            dot8r<32>(za, wa, 8 * ZSTR * 4, 8 * W1STR * 4, acc);
            kreduce8(acc, ks);
            int r = oct * 8 + ks;
            float* pb = smf + OFF_PB1 + kh * (16 * PBS) + r * PBS + bq * 4;
            *(unsigned long long*)(pb)     = acc[0];
            *(unsigned long long*)(pb + 2) = acc[1];
        } else if (wid < 10) {
            const int oct = wid - 4;
            unsigned long long acc[16] = {0,0,0,0,0,0,0,0,0,0,0,0,0,0,0,0};
            uint32_t za = smb + (OFF_Z  + (256 + ks) * ZSTR + bq * 4) * 4;
            uint32_t wa = smb + (OFF_W2 + ks * W2STR + oct * 8) * 4;
            dot8r<32>(za, wa, 8 * ZSTR * 4, 8 * W2STR * 4, acc);
            kreduce8(acc, ks);
            int r = oct * 8 + ks;
            unsigned long long bias2 = dup2(smf[OFF_BHH + r]);
            ADD2(acc[0], bias2); ADD2(acc[1], bias2);
            float* gp = smf + OFF_GH + r * GHSTR + bq * 4;
            *(unsigned long long*)(gp)     = acc[0];
            *(unsigned long long*)(gp + 2) = acc[1];
        }
        __syncthreads();

        // ---- xg = x * sigmoid(A1) -> g_xg ----
        if (tid < 256) {
            int rr = tid & 15, bb = tid >> 4;
            float s = smf[OFF_PB1 + rr * PBS + bb]
                    + smf[OFF_PB1 + 16 * PBS + rr * PBS + bb]
                    + smf[OFF_BA + rr];
            float a  = sigmoidf_(s);
            float xv = smf[OFF_Z + (g * 16 + rr) * ZSTR + bb];
            g_xg[(p * 16 + bb) * 256 + g * 16 + rr] = xv * a;
        }

        ++barn; pbar(base_sm, p, g, barn);   // xg published (gh is CTA-local)

        // ---- stage xg -> zT x-region ----
        for (int idx = tid; idx < 1024; idx += NTHR) {
            int bb = idx & 15, q4 = idx >> 4;
            float4 v = *(const float4*)&g_xg[(p * 16 + bb) * 256 + q4 * 4];
            int base = OFF_Z + (q4 * 4) * ZSTR + bb;
            smf[base] = v.x; smf[base + ZSTR] = v.y;
            smf[base + 2 * ZSTR] = v.z; smf[base + 3 * ZSTR] = v.w;
        }
        __syncthreads();

        // ===== C dot: 12 warps = 6 oct x 2 kh, K=256 =====
        {
            const int oct = wid >> 1, kh = wid & 1;
            unsigned long long acc[16] = {0,0,0,0,0,0,0,0,0,0,0,0,0,0,0,0};
            uint32_t za = smb + (OFF_Z  + (kh * 128 + ks) * ZSTR  + bq * 4) * 4;
            uint32_t wa = smb + (OFF_WC + (kh * 128 + ks) * WCSTR + oct * 8) * 4;
            dot8r<16>(za, wa, 8 * ZSTR * 4, 8 * WCSTR * 4, acc);
            kreduce8(acc, ks);
            int r = oct * 8 + ks;
            float* pb = smf + OFF_PBC + kh * (48 * PBS) + r * PBS + bq * 4;
            *(unsigned long long*)(pb)     = acc[0];
            *(unsigned long long*)(pb + 2) = acc[1];
        }
        __syncthreads();

        // ---- epilogue: gates + h update (all SMEM-local) ----
        if (tid < 256) {
            int jj = tid & 15, bb = tid >> 4;
            int b  = p * 16 + bb;
            int j  = g * 16 + jj;
            float hp = smf[OFF_Z + (256 + j) * ZSTR + bb];
            float gi[3], gh_[3];
#pragma unroll
            for (int gate = 0; gate < 3; ++gate) {
                int r = gate * 16 + jj;
                gi[gate] = smf[OFF_PBC + r * PBS + bb]
                         + smf[OFF_PBC + 48 * PBS + r * PBS + bb]
                         + smf[OFF_BIH + r];
                gh_[gate] = smf[OFF_GH + r * GHSTR + bb];
            }
            float r_ = sigmoidf_(gi[0] + gh_[0]);
            float z_ = sigmoidf_(gi[1] + gh_[1]);
            float n_ = tanhf(gi[2] + r_ * gh_[2]);
            float hn = (1.0f - z_) * n_ + z_ * hp;
            g_h[b * 256 + j] = hn;
            out[(b * S_LEN + t) * 256 + j] = hn;
        }

        // ---- prefetch x(t+1) -> zT x-region (overlaps epilogue + barrier) --
        if (t + 1 < S_LEN) {
            for (int idx = tid; idx < 1024; idx += NTHR) {
                int bb = idx & 15, q4 = idx >> 4;
                float4 v = *(const float4*)
                    &x[((p * 16 + bb) * S_LEN + (t + 1)) * 256 + q4 * 4];
                int base = OFF_Z + (q4 * 4) * ZSTR + bb;
                smf[base] = v.x; smf[base + ZSTR] = v.y;
                smf[base + 2 * ZSTR] = v.z; smf[base + 3 * ZSTR] = v.w;
            }
        }

        ++barn; pbar(base_sm, p, g, barn);   // h_new published
    }
}

extern "C" void kernel_launch(void* const* d_in, const int* in_sizes, int n_in,
                              void* d_out, int out_size) {
    const float* x     = (const float*)d_in[0];
    const float* hid   = (const float*)d_in[1];
    const float* W_att = (const float*)d_in[2];
    const float* b_att = (const float*)d_in[3];
    const float* w_ih  = (const float*)d_in[4];
    const float* b_ih  = (const float*)d_in[5];
    const float* w_hh  = (const float*)d_in[6];
    const float* b_hh  = (const float*)d_in[7];
    float* out = (float*)d_out;

    cudaFuncSetAttribute(gru_att_persistent,
                         cudaFuncAttributeMaxDynamicSharedMemorySize, SMEM_BYTES);

    gru_att_persistent<<<NBLK, NTHR, SMEM_BYTES>>>(
        x, hid, W_att, b_att, w_ih, b_ih, w_hh, b_hh, out);
}

// round 8
// speedup vs baseline: 1.2023x; 1.0298x over previous
#include <cuda_runtime.h>
#include <cstdint>

// ============================================================================
// GRU_Att_Layer R8: R7 structure at 512 threads (16 warps) for latency hiding.
//  - 8row x 4batch dot tiles (1-wf w loads, 4-wf z loads), shfl k-reduce
//  - A1: warps 0-3; A2: warps 4-15 (6 oct x 2 kh); C: warps 0-11 (6 oct x 2 kh)
//  - gh = 2 kh-partials combined in epilogue
//  - conflict-free transposed staging; flag-array group barrier
// B=128,S=1024,I=256,H=256. 128 CTAs: g=blockIdx&15 rows, p=blockIdx>>4.
// ============================================================================

#define S_LEN 1024
#define NBLK  128
#define NTHR  512

#define ZSTR  20
#define W1STR 20
#define W2STR 52
#define WCSTR 52
#define PBS   18     // partial row stride (16 batches + 2 pad)

// SMEM layout (float offsets)
#define OFF_W1   0                        // [512][20]  W_att^T (16 rows)
#define OFF_W2   (OFF_W1 + 512*W1STR)     // 10240 [256][52] w_hh^T gate-triples
#define OFF_WC   (OFF_W2 + 256*W2STR)     // 23552 [256][52] w_ih^T gate-triples
#define OFF_Z    (OFF_WC + 256*WCSTR)     // 36864 [512][20] zT=[x|xg ; h]^T
#define OFF_PB2  (OFF_Z  + 512*ZSTR)      // 47104 [2][48][18] gh partials
#define OFF_PB1  (OFF_PB2 + 2*48*PBS)     // 48832 [2][16][18] A1 partials
#define OFF_PBC  (OFF_PB1 + 2*16*PBS)     // 49408 [2][48][18] C partials
#define OFF_BA   (OFF_PBC + 2*48*PBS)     // 51136
#define OFF_BHH  (OFF_BA + 16)
#define OFF_BIH  (OFF_BHH + 48)
#define OFF_BASE (OFF_BIH + 48)           // 51248: 16 barrier bases (as uint)
#define SMEM_FLOATS (OFF_BASE + 16)       // 51264
#define SMEM_BYTES  (SMEM_FLOATS * 4)     // 205056 B < 227 KB opt-in

// ---------------- scratch (device globals; allocation forbidden) -----------
__device__ __align__(16) float g_h [128 * 256];
__device__ __align__(16) float g_xg[128 * 256];
__device__ unsigned g_flag[NBLK * 32];   // per-CTA epoch, own sector

// ---------------- barrier: per-CTA epoch flags, 16 pollers ------------------
__device__ __forceinline__ void pbar(const unsigned* base_sm, int p, int g,
                                     unsigned n) {
    __syncthreads();
    if (threadIdx.x == 0) {
        __threadfence();
        *(volatile unsigned*)&g_flag[blockIdx.x * 32] = base_sm[g] + n;
    }
    if (threadIdx.x < 16) {
        volatile unsigned* f = &g_flag[(p * 16 + threadIdx.x) * 32];
        unsigned tgt = base_sm[threadIdx.x] + n;
        while ((int)(*f - tgt) < 0) { }
        __threadfence();
    }
    __syncthreads();
}

__device__ __forceinline__ float sigmoidf_(float x) {
    return 1.0f / (1.0f + __expf(-x));
}
__device__ __forceinline__ uint32_t sm_u32(const void* ptr) {
    uint32_t a;
    asm("{ .reg .u64 t; cvta.to.shared.u64 t, %1; cvt.u32.u64 %0, t; }"
        : "=r"(a) : "l"(ptr));
    return a;
}
__device__ __forceinline__ unsigned long long dup2(float w) {
    unsigned long long d; uint32_t u = __float_as_uint(w);
    asm("mov.b64 %0, {%1,%1};" : "=l"(d) : "r"(u));
    return d;
}
#define FMA2(acc, a, b) \
    asm("fma.rn.f32x2 %0, %1, %2, %0;" : "+l"(acc) : "l"(a), "l"(b))
#define ADD2(d, s) \
    asm("add.rn.f32x2 %0, %0, %1;" : "+l"(d) : "l"(s))

// 8-row x 4-batch dot. lane=(ks=lane&7, bq=lane>>3). One k per iter per lane.
template <int NITER>
__device__ __forceinline__ void dot8r(uint32_t za, uint32_t wa,
                                      int zstep, int wstep,
                                      unsigned long long acc[16]) {
#pragma unroll 4
    for (int i = 0; i < NITER; ++i) {
        unsigned long long z01, z23;
        asm volatile("ld.shared.v2.b64 {%0,%1}, [%2];"
                     : "=l"(z01), "=l"(z23) : "r"(za));
        float w0, w1, w2, w3, w4, w5, w6, w7;
        asm volatile("ld.shared.v4.f32 {%0,%1,%2,%3}, [%4];"
                     : "=f"(w0), "=f"(w1), "=f"(w2), "=f"(w3) : "r"(wa));
        asm volatile("ld.shared.v4.f32 {%0,%1,%2,%3}, [%4];"
                     : "=f"(w4), "=f"(w5), "=f"(w6), "=f"(w7) : "r"(wa + 16));
        unsigned long long d;
        d = dup2(w0); FMA2(acc[0],  d, z01); FMA2(acc[1],  d, z23);
        d = dup2(w1); FMA2(acc[2],  d, z01); FMA2(acc[3],  d, z23);
        d = dup2(w2); FMA2(acc[4],  d, z01); FMA2(acc[5],  d, z23);
        d = dup2(w3); FMA2(acc[6],  d, z01); FMA2(acc[7],  d, z23);
        d = dup2(w4); FMA2(acc[8],  d, z01); FMA2(acc[9],  d, z23);
        d = dup2(w5); FMA2(acc[10], d, z01); FMA2(acc[11], d, z23);
        d = dup2(w6); FMA2(acc[12], d, z01); FMA2(acc[13], d, z23);
        d = dup2(w7); FMA2(acc[14], d, z01); FMA2(acc[15], d, z23);
        za += zstep; wa += wstep;
    }
}

// shfl tree-reduce over ks (8 lanes). After: acc[0]=batches(bq*4+0,1),
// acc[1]=batches(bq*4+2,3) for local row == ks.
__device__ __forceinline__ void kreduce8(unsigned long long acc[16], int ks) {
    const bool h4 = (ks & 4) != 0;
#pragma unroll
    for (int r = 0; r < 4; ++r)
#pragma unroll
        for (int bp = 0; bp < 2; ++bp) {
            unsigned long long snd = h4 ? acc[r*2+bp] : acc[(r+4)*2+bp];
            unsigned long long kpt = h4 ? acc[(r+4)*2+bp] : acc[r*2+bp];
            unsigned long long rcv = __shfl_xor_sync(0xffffffffu, snd, 4);
            ADD2(kpt, rcv);
            acc[r*2+bp] = kpt;
        }
    const bool h2 = (ks & 2) != 0;
#pragma unroll
    for (int r = 0; r < 2; ++r)
#pragma unroll
        for (int bp = 0; bp < 2; ++bp) {
            unsigned long long snd = h2 ? acc[r*2+bp] : acc[(r+2)*2+bp];
            unsigned long long kpt = h2 ? acc[(r+2)*2+bp] : acc[r*2+bp];
            unsigned long long rcv = __shfl_xor_sync(0xffffffffu, snd, 2);
            ADD2(kpt, rcv);
            acc[r*2+bp] = kpt;
        }
    const bool h1 = (ks & 1) != 0;
#pragma unroll
    for (int bp = 0; bp < 2; ++bp) {
        unsigned long long snd = h1 ? acc[bp] : acc[2+bp];
        unsigned long long kpt = h1 ? acc[2+bp] : acc[bp];
        unsigned long long rcv = __shfl_xor_sync(0xffffffffu, snd, 1);
        ADD2(kpt, rcv);
        acc[bp] = kpt;
    }
}

__global__ void __launch_bounds__(NTHR, 1)
gru_att_persistent(const float* __restrict__ x,      // [B,S,I]
                   const float* __restrict__ hid,    // [B,H]
                   const float* __restrict__ W_att,  // [256,512]
                   const float* __restrict__ b_att,  // [256]
                   const float* __restrict__ w_ih,   // [768,256]
                   const float* __restrict__ b_ih,   // [768]
                   const float* __restrict__ w_hh,   // [768,256]
                   const float* __restrict__ b_hh,   // [768]
                   float* __restrict__ out)          // [B,S,H]
{
    extern __shared__ float smf[];
    const int tid  = threadIdx.x;
    const int g    = blockIdx.x & 15;
    const int p    = blockIdx.x >> 4;
    const int wid  = tid >> 5;
    const int lane = tid & 31;
    const int ks   = lane & 7;
    const int bq   = lane >> 3;
    const uint32_t smb = sm_u32(smf);
    unsigned* base_sm = (unsigned*)(smf + OFF_BASE);

    if (tid < 16) base_sm[tid] = g_flag[(p * 16 + tid) * 32];

    // ---- stage weights (transposed, gate-triple row sets) ----
    for (int idx = tid; idx < 512 * 16; idx += NTHR) {
        int k = idx >> 4, rr = idx & 15;
        smf[OFF_W1 + k * W1STR + rr] = W_att[(g * 16 + rr) * 512 + k];
    }
    for (int idx = tid; idx < 256 * 48; idx += NTHR) {
        int k = idx / 48, rl = idx % 48;
        int gate = rl >> 4, jj = rl & 15;
        smf[OFF_W2 + k * W2STR + rl] = w_hh[(gate * 256 + g * 16 + jj) * 256 + k];
    }
    for (int idx = tid; idx < 256 * 48; idx += NTHR) {
        int k = idx / 48, rl = idx % 48;
        int gate = rl >> 4, jj = rl & 15;
        smf[OFF_WC + k * WCSTR + rl] = w_ih[(gate * 256 + g * 16 + jj) * 256 + k];
    }
    if (tid < 16) smf[OFF_BA + tid] = b_att[g * 16 + tid];
    if (tid < 48) {
        int gate = tid >> 4, jj = tid & 15;
        smf[OFF_BHH + tid] = b_hh[gate * 256 + g * 16 + jj];
        smf[OFF_BIH + tid] = b_ih[gate * 256 + g * 16 + jj];
    }

    // ---- init hidden state (one writer block per batch group) ----
    if (g == 0) {
        for (int idx = tid; idx < 16 * 256; idx += NTHR) {
            int bb = idx >> 8, k = idx & 255;
            g_h[(p * 16 + bb) * 256 + k] = hid[(p * 16 + bb) * 256 + k];
        }
    }

    // ---- prefetch x(t=0) -> zT x-region (conflict-free: lane==batch) ----
    for (int idx = tid; idx < 1024; idx += NTHR) {
        int bb = idx & 15, q4 = idx >> 4;
        float4 v = *(const float4*)&x[((p * 16 + bb) * S_LEN + 0) * 256 + q4 * 4];
        int base = OFF_Z + (q4 * 4) * ZSTR + bb;
        smf[base] = v.x; smf[base + ZSTR] = v.y;
        smf[base + 2 * ZSTR] = v.z; smf[base + 3 * ZSTR] = v.w;
    }

    unsigned barn = 1;
    pbar(base_sm, p, g, barn);

    for (int t = 0; t < S_LEN; ++t) {
        // ---- stage h -> zT[256+k][bb] ----
        for (int idx = tid; idx < 1024; idx += NTHR) {
            int bb = idx & 15, q4 = idx >> 4;
            float4 v = *(const float4*)&g_h[(p * 16 + bb) * 256 + q4 * 4];
            int base = OFF_Z + (256 + q4 * 4) * ZSTR + bb;
            smf[base] = v.x; smf[base + ZSTR] = v.y;
            smf[base + 2 * ZSTR] = v.z; smf[base + 3 * ZSTR] = v.w;
        }
        __syncthreads();

        // ===== dot1: warps 0-3 A1 (2oct x 2kh, K=512); warps 4-15 A2
        //       (6oct x 2kh, K=256) =====
        if (wid < 4) {
            const int oct = wid >> 1, kh = wid & 1;
            unsigned long long acc[16] = {0,0,0,0,0,0,0,0,0,0,0,0,0,0,0,0};
            uint32_t za = smb + (OFF_Z  + (kh * 256 + ks) * ZSTR  + bq * 4) * 4;
            uint32_t wa = smb + (OFF_W1 + (kh * 256 + ks) * W1STR + oct * 8) * 4;
            dot8r<32>(za, wa, 8 * ZSTR * 4, 8 * W1STR * 4, acc);
            kreduce8(acc, ks);
            int r = oct * 8 + ks;
            float* pb = smf + OFF_PB1 + kh * (16 * PBS) + r * PBS + bq * 4;
            *(unsigned long long*)(pb)     = acc[0];
            *(unsigned long long*)(pb + 2) = acc[1];
        } else {
            const int a2 = wid - 4;
            const int oct = a2 >> 1, kh = a2 & 1;
            unsigned long long acc[16] = {0,0,0,0,0,0,0,0,0,0,0,0,0,0,0,0};
            uint32_t za = smb + (OFF_Z  + (256 + kh * 128 + ks) * ZSTR + bq * 4) * 4;
            uint32_t wa = smb + (OFF_W2 + (kh * 128 + ks) * W2STR + oct * 8) * 4;
            dot8r<16>(za, wa, 8 * ZSTR * 4, 8 * W2STR * 4, acc);
            kreduce8(acc, ks);
            int r = oct * 8 + ks;
            float* pb = smf + OFF_PB2 + kh * (48 * PBS) + r * PBS + bq * 4;
            *(unsigned long long*)(pb)     = acc[0];
            *(unsigned long long*)(pb + 2) = acc[1];
        }
        __syncthreads();

        // ---- xg = x * sigmoid(A1) -> g_xg ----
        if (tid < 256) {
            int rr = tid & 15, bb = tid >> 4;
            float s = smf[OFF_PB1 + rr * PBS + bb]
                    + smf[OFF_PB1 + 16 * PBS + rr * PBS + bb]
                    + smf[OFF_BA + rr];
            float a  = sigmoidf_(s);
            float xv = smf[OFF_Z + (g * 16 + rr) * ZSTR + bb];
            g_xg[(p * 16 + bb) * 256 + g * 16 + rr] = xv * a;
        }

        ++barn; pbar(base_sm, p, g, barn);   // xg published (gh partials local)

        // ---- stage xg -> zT x-region ----
        for (int idx = tid; idx < 1024; idx += NTHR) {
            int bb = idx & 15, q4 = idx >> 4;
            float4 v = *(const float4*)&g_xg[(p * 16 + bb) * 256 + q4 * 4];
            int base = OFF_Z + (q4 * 4) * ZSTR + bb;
            smf[base] = v.x; smf[base + ZSTR] = v.y;
            smf[base + 2 * ZSTR] = v.z; smf[base + 3 * ZSTR] = v.w;
        }
        __syncthreads();

        // ===== C dot: warps 0-11 (6oct x 2kh, K=256); warps 12-15 skip =====
        if (wid < 12) {
            const int oct = wid >> 1, kh = wid & 1;
            unsigned long long acc[16] = {0,0,0,0,0,0,0,0,0,0,0,0,0,0,0,0};
            uint32_t za = smb + (OFF_Z  + (kh * 128 + ks) * ZSTR  + bq * 4) * 4;
            uint32_t wa = smb + (OFF_WC + (kh * 128 + ks) * WCSTR + oct * 8) * 4;
            dot8r<16>(za, wa, 8 * ZSTR * 4, 8 * WCSTR * 4, acc);
            kreduce8(acc, ks);
            int r = oct * 8 + ks;
            float* pb = smf + OFF_PBC + kh * (48 * PBS) + r * PBS + bq * 4;
            *(unsigned long long*)(pb)     = acc[0];
            *(unsigned long long*)(pb + 2) = acc[1];
        }
        __syncthreads();

        // ---- epilogue: gates + h update (all SMEM-local) ----
        if (tid < 256) {
            int jj = tid & 15, bb = tid >> 4;
            int b  = p * 16 + bb;
            int j  = g * 16 + jj;
            float hp = smf[OFF_Z + (256 + j) * ZSTR + bb];
            float gi[3], gh_[3];
#pragma unroll
            for (int gate = 0; gate < 3; ++gate) {
                int r = gate * 16 + jj;
                gi[gate] = smf[OFF_PBC + r * PBS + bb]
                         + smf[OFF_PBC + 48 * PBS + r * PBS + bb]
                         + smf[OFF_BIH + r];
                gh_[gate] = smf[OFF_PB2 + r * PBS + bb]
                          + smf[OFF_PB2 + 48 * PBS + r * PBS + bb]
                          + smf[OFF_BHH + r];
            }
            float r_ = sigmoidf_(gi[0] + gh_[0]);
            float z_ = sigmoidf_(gi[1] + gh_[1]);
            float n_ = tanhf(gi[2] + r_ * gh_[2]);
            float hn = (1.0f - z_) * n_ + z_ * hp;
            g_h[b * 256 + j] = hn;
            out[(b * S_LEN + t) * 256 + j] = hn;
        }

        // ---- prefetch x(t+1) -> zT x-region (overlaps epilogue + barrier) --
        if (t + 1 < S_LEN) {
            for (int idx = tid; idx < 1024; idx += NTHR) {
                int bb = idx & 15, q4 = idx >> 4;
                float4 v = *(const float4*)
                    &x[((p * 16 + bb) * S_LEN + (t + 1)) * 256 + q4 * 4];
                int base = OFF_Z + (q4 * 4) * ZSTR + bb;
                smf[base] = v.x; smf[base + ZSTR] = v.y;
                smf[base + 2 * ZSTR] = v.z; smf[base + 3 * ZSTR] = v.w;
            }
        }

        ++barn; pbar(base_sm, p, g, barn);   // h_new published
    }
}

extern "C" void kernel_launch(void* const* d_in, const int* in_sizes, int n_in,
                              void* d_out, int out_size) {
    const float* x     = (const float*)d_in[0];
    const float* hid   = (const float*)d_in[1];
    const float* W_att = (const float*)d_in[2];
    const float* b_att = (const float*)d_in[3];
    const float* w_ih  = (const float*)d_in[4];
    const float* b_ih  = (const float*)d_in[5];
    const float* w_hh  = (const float*)d_in[6];
    const float* b_hh  = (const float*)d_in[7];
    float* out = (float*)d_out;

    cudaFuncSetAttribute(gru_att_persistent,
                         cudaFuncAttributeMaxDynamicSharedMemorySize, SMEM_BYTES);

    gru_att_persistent<<<NBLK, NTHR, SMEM_BYTES>>>(
        x, hid, W_att, b_att, w_ih, b_ih, w_hh, b_hh, out);
}

// round 9
// speedup vs baseline: 1.2265x; 1.0201x over previous
#include <cuda_runtime.h>
#include <cstdint>

// ============================================================================
// GRU_Att_Layer R9: software-pipelined A1x.
//  - A1 x-part (K=256, h-independent) for step t+1 computed by warps 12-15
//    during step t's C phase -> post-barrier dot1 is K=256 and balanced.
//  - one prologue burst stages h, x(t+1)->xnext, xv(t) (single L2 exposure)
//  - 8row x 4batch dot tiles, shfl k-reduce, conflict-free staging
//  - flag-array 16-CTA group barrier (2 per step)
// B=128,S=1024,I=256,H=256. 128 CTAs: g=blockIdx&15 rows, p=blockIdx>>4.
// 512 threads.
// ============================================================================

#define S_LEN 1024
#define NBLK  128
#define NTHR  512

#define ZSTR  20
#define W1STR 20
#define W2STR 52
#define WCSTR 52
#define PBS   18
#define XVS   18

// SMEM layout (float offsets)
#define OFF_W1   0                        // [512][20] W_att^T (16 rows)
#define OFF_W2   (OFF_W1 + 512*W1STR)     // 10240 [256][52] w_hh^T triples
#define OFF_WC   (OFF_W2 + 256*W2STR)     // 23552 [256][52] w_ih^T triples
#define OFF_Z    (OFF_WC + 256*WCSTR)     // 36864 [512][20]: [xg ; h]^T
#define OFF_XN   (OFF_Z  + 512*ZSTR)      // 47104 [256][20] x(t+1)^T
#define OFF_PB2  (OFF_XN + 256*ZSTR)      // 52224 [2][48][18] gh partials
#define OFF_PB1H (OFF_PB2 + 2*48*PBS)     // 53952 [2][16][18]
#define OFF_PB1X (OFF_PB1H + 2*16*PBS)    // 54528 [2][16][18]
#define OFF_PBC  (OFF_PB1X + 2*16*PBS)    // 55104 [2][48][18]
#define OFF_XV   (OFF_PBC + 2*48*PBS)     // 56832 [16][18]
#define OFF_BA   (OFF_XV + 16*XVS)        // 57120
#define OFF_BHH  (OFF_BA + 16)
#define OFF_BIH  (OFF_BHH + 48)
#define OFF_BASE (OFF_BIH + 48)           // 57232: 16 barrier bases
#define SMEM_FLOATS (OFF_BASE + 16)       // 57248
#define SMEM_BYTES  (SMEM_FLOATS * 4)     // 228992 B <= 227KB opt-in

// ---------------- scratch (device globals; allocation forbidden) -----------
__device__ __align__(16) float g_h [128 * 256];
__device__ __align__(16) float g_xg[128 * 256];
__device__ unsigned g_flag[NBLK * 32];

// ---------------- barrier: per-CTA epoch flags, 16 pollers ------------------
__device__ __forceinline__ void pbar(const unsigned* base_sm, int p, int g,
                                     unsigned n) {
    __syncthreads();
    if (threadIdx.x == 0) {
        __threadfence();
        *(volatile unsigned*)&g_flag[blockIdx.x * 32] = base_sm[g] + n;
    }
    if (threadIdx.x < 16) {
        volatile unsigned* f = &g_flag[(p * 16 + threadIdx.x) * 32];
        unsigned tgt = base_sm[threadIdx.x] + n;
        while ((int)(*f - tgt) < 0) { }
        __threadfence();
    }
    __syncthreads();
}

__device__ __forceinline__ float sigmoidf_(float x) {
    return 1.0f / (1.0f + __expf(-x));
}
__device__ __forceinline__ uint32_t sm_u32(const void* ptr) {
    uint32_t a;
    asm("{ .reg .u64 t; cvta.to.shared.u64 t, %1; cvt.u32.u64 %0, t; }"
        : "=r"(a) : "l"(ptr));
    return a;
}
__device__ __forceinline__ unsigned long long dup2(float w) {
    unsigned long long d; uint32_t u = __float_as_uint(w);
    asm("mov.b64 %0, {%1,%1};" : "=l"(d) : "r"(u));
    return d;
}
#define FMA2(acc, a, b) \
    asm("fma.rn.f32x2 %0, %1, %2, %0;" : "+l"(acc) : "l"(a), "l"(b))
#define ADD2(d, s) \
    asm("add.rn.f32x2 %0, %0, %1;" : "+l"(d) : "l"(s))

// 8-row x 4-batch dot. lane=(ks=lane&7, bq=lane>>3).
template <int NITER>
__device__ __forceinline__ void dot8r(uint32_t za, uint32_t wa,
                                      int zstep, int wstep,
                                      unsigned long long acc[16]) {
#pragma unroll 4
    for (int i = 0; i < NITER; ++i) {
        unsigned long long z01, z23;
        asm volatile("ld.shared.v2.b64 {%0,%1}, [%2];"
                     : "=l"(z01), "=l"(z23) : "r"(za));
        float w0, w1, w2, w3, w4, w5, w6, w7;
        asm volatile("ld.shared.v4.f32 {%0,%1,%2,%3}, [%4];"
                     : "=f"(w0), "=f"(w1), "=f"(w2), "=f"(w3) : "r"(wa));
        asm volatile("ld.shared.v4.f32 {%0,%1,%2,%3}, [%4];"
                     : "=f"(w4), "=f"(w5), "=f"(w6), "=f"(w7) : "r"(wa + 16));
        unsigned long long d;
        d = dup2(w0); FMA2(acc[0],  d, z01); FMA2(acc[1],  d, z23);
        d = dup2(w1); FMA2(acc[2],  d, z01); FMA2(acc[3],  d, z23);
        d = dup2(w2); FMA2(acc[4],  d, z01); FMA2(acc[5],  d, z23);
        d = dup2(w3); FMA2(acc[6],  d, z01); FMA2(acc[7],  d, z23);
        d = dup2(w4); FMA2(acc[8],  d, z01); FMA2(acc[9],  d, z23);
        d = dup2(w5); FMA2(acc[10], d, z01); FMA2(acc[11], d, z23);
        d = dup2(w6); FMA2(acc[12], d, z01); FMA2(acc[13], d, z23);
        d = dup2(w7); FMA2(acc[14], d, z01); FMA2(acc[15], d, z23);
        za += zstep; wa += wstep;
    }
}

// shfl tree-reduce over ks (8 lanes): acc[0]=batches(bq*4+0,1),
// acc[1]=batches(bq*4+2,3) for local row == ks.
__device__ __forceinline__ void kreduce8(unsigned long long acc[16], int ks) {
    const bool h4 = (ks & 4) != 0;
#pragma unroll
    for (int r = 0; r < 4; ++r)
#pragma unroll
        for (int bp = 0; bp < 2; ++bp) {
            unsigned long long snd = h4 ? acc[r*2+bp] : acc[(r+4)*2+bp];
            unsigned long long kpt = h4 ? acc[(r+4)*2+bp] : acc[r*2+bp];
            unsigned long long rcv = __shfl_xor_sync(0xffffffffu, snd, 4);
            ADD2(kpt, rcv);
            acc[r*2+bp] = kpt;
        }
    const bool h2 = (ks & 2) != 0;
#pragma unroll
    for (int r = 0; r < 2; ++r)
#pragma unroll
        for (int bp = 0; bp < 2; ++bp) {
            unsigned long long snd = h2 ? acc[r*2+bp] : acc[(r+2)*2+bp];
            unsigned long long kpt = h2 ? acc[(r+2)*2+bp] : acc[r*2+bp];
            unsigned long long rcv = __shfl_xor_sync(0xffffffffu, snd, 2);
            ADD2(kpt, rcv);
            acc[r*2+bp] = kpt;
        }
    const bool h1 = (ks & 1) != 0;
#pragma unroll
    for (int bp = 0; bp < 2; ++bp) {
        unsigned long long snd = h1 ? acc[bp] : acc[2+bp];
        unsigned long long kpt = h1 ? acc[2+bp] : acc[bp];
        unsigned long long rcv = __shfl_xor_sync(0xffffffffu, snd, 1);
        ADD2(kpt, rcv);
        acc[bp] = kpt;
    }
}

__global__ void __launch_bounds__(NTHR, 1)
gru_att_persistent(const float* __restrict__ x,      // [B,S,I]
                   const float* __restrict__ hid,    // [B,H]
                   const float* __restrict__ W_att,  // [256,512]
                   const float* __restrict__ b_att,  // [256]
                   const float* __restrict__ w_ih,   // [768,256]
                   const float* __restrict__ b_ih,   // [768]
                   const float* __restrict__ w_hh,   // [768,256]
                   const float* __restrict__ b_hh,   // [768]
                   float* __restrict__ out)          // [B,S,H]
{
    extern __shared__ float smf[];
    const int tid  = threadIdx.x;
    const int g    = blockIdx.x & 15;
    const int p    = blockIdx.x >> 4;
    const int wid  = tid >> 5;
    const int lane = tid & 31;
    const int ks   = lane & 7;
    const int bq   = lane >> 3;
    const uint32_t smb = sm_u32(smf);
    unsigned* base_sm = (unsigned*)(smf + OFF_BASE);

    if (tid < 16) base_sm[tid] = g_flag[(p * 16 + tid) * 32];

    // ---- stage weights (transposed, gate-triple row sets) ----
    for (int idx = tid; idx < 512 * 16; idx += NTHR) {
        int k = idx >> 4, rr = idx & 15;
        smf[OFF_W1 + k * W1STR + rr] = W_att[(g * 16 + rr) * 512 + k];
    }
    for (int idx = tid; idx < 256 * 48; idx += NTHR) {
        int k = idx / 48, rl = idx % 48;
        int gate = rl >> 4, jj = rl & 15;
        smf[OFF_W2 + k * W2STR + rl] = w_hh[(gate * 256 + g * 16 + jj) * 256 + k];
    }
    for (int idx = tid; idx < 256 * 48; idx += NTHR) {
        int k = idx / 48, rl = idx % 48;
        int gate = rl >> 4, jj = rl & 15;
        smf[OFF_WC + k * WCSTR + rl] = w_ih[(gate * 256 + g * 16 + jj) * 256 + k];
    }
    if (tid < 16) smf[OFF_BA + tid] = b_att[g * 16 + tid];
    if (tid < 48) {
        int gate = tid >> 4, jj = tid & 15;
        smf[OFF_BHH + tid] = b_hh[gate * 256 + g * 16 + jj];
        smf[OFF_BIH + tid] = b_ih[gate * 256 + g * 16 + jj];
    }

    // ---- init hidden state ----
    if (g == 0) {
        for (int idx = tid; idx < 16 * 256; idx += NTHR) {
            int bb = idx >> 8, k = idx & 255;
            g_h[(p * 16 + bb) * 256 + k] = hid[(p * 16 + bb) * 256 + k];
        }
    }

    // ---- pre-loop: stage x(0) -> XN, then A1x(0) (warps 12-15) ----
    for (int idx = tid; idx < 1024; idx += NTHR) {
        int bb = idx & 15, q4 = idx >> 4;
        float4 v = *(const float4*)&x[((p * 16 + bb) * S_LEN + 0) * 256 + q4 * 4];
        int base = OFF_XN + (q4 * 4) * ZSTR + bb;
        smf[base] = v.x; smf[base + ZSTR] = v.y;
        smf[base + 2 * ZSTR] = v.z; smf[base + 3 * ZSTR] = v.w;
    }
    __syncthreads();
    if (wid >= 12) {
        const int a = wid - 12, oct = a >> 1, kh = a & 1;
        unsigned long long acc[16] = {0,0,0,0,0,0,0,0,0,0,0,0,0,0,0,0};
        uint32_t za = smb + (OFF_XN + (kh * 128 + ks) * ZSTR  + bq * 4) * 4;
        uint32_t wa = smb + (OFF_W1 + (kh * 128 + ks) * W1STR + oct * 8) * 4;
        dot8r<16>(za, wa, 8 * ZSTR * 4, 8 * W1STR * 4, acc);
        kreduce8(acc, ks);
        int r = oct * 8 + ks;
        float* pb = smf + OFF_PB1X + kh * (16 * PBS) + r * PBS + bq * 4;
        *(unsigned long long*)(pb)     = acc[0];
        *(unsigned long long*)(pb + 2) = acc[1];
    }

    unsigned barn = 1;
    pbar(base_sm, p, g, barn);

    for (int t = 0; t < S_LEN; ++t) {
        // ==== prologue burst: h -> zT-h, x(t+1) -> XN, xv(t) -> XV ====
        for (int idx = tid; idx < 1024; idx += NTHR) {
            int bb = idx & 15, q4 = idx >> 4;
            float4 v = *(const float4*)&g_h[(p * 16 + bb) * 256 + q4 * 4];
            int base = OFF_Z + (256 + q4 * 4) * ZSTR + bb;
            smf[base] = v.x; smf[base + ZSTR] = v.y;
            smf[base + 2 * ZSTR] = v.z; smf[base + 3 * ZSTR] = v.w;
        }
        if (t + 1 < S_LEN) {
            for (int idx = tid; idx < 1024; idx += NTHR) {
                int bb = idx & 15, q4 = idx >> 4;
                float4 v = *(const float4*)
                    &x[((p * 16 + bb) * S_LEN + (t + 1)) * 256 + q4 * 4];
                int base = OFF_XN + (q4 * 4) * ZSTR + bb;
                smf[base] = v.x; smf[base + ZSTR] = v.y;
                smf[base + 2 * ZSTR] = v.z; smf[base + 3 * ZSTR] = v.w;
            }
        }
        if (tid < 64) {   // xv(t): x[b][t][g*16 + rq*4 .. +3]
            int bb = tid & 15, rq = tid >> 4;
            float4 v = *(const float4*)
                &x[((p * 16 + bb) * S_LEN + t) * 256 + g * 16 + rq * 4];
            int base = OFF_XV + (rq * 4) * XVS + bb;
            smf[base] = v.x; smf[base + XVS] = v.y;
            smf[base + 2 * XVS] = v.z; smf[base + 3 * XVS] = v.w;
        }
        __syncthreads();

        // ==== dot1 (balanced, K=256 each): A1h warps 0-3, A2 warps 4-15 ====
        if (wid < 4) {
            const int oct = wid >> 1, kh = wid & 1;
            unsigned long long acc[16] = {0,0,0,0,0,0,0,0,0,0,0,0,0,0,0,0};
            uint32_t za = smb + (OFF_Z  + (256 + kh * 128 + ks) * ZSTR + bq * 4) * 4;
            uint32_t wa = smb + (OFF_W1 + (256 + kh * 128 + ks) * W1STR + oct * 8) * 4;
            dot8r<16>(za, wa, 8 * ZSTR * 4, 8 * W1STR * 4, acc);
            kreduce8(acc, ks);
            int r = oct * 8 + ks;
            float* pb = smf + OFF_PB1H + kh * (16 * PBS) + r * PBS + bq * 4;
            *(unsigned long long*)(pb)     = acc[0];
            *(unsigned long long*)(pb + 2) = acc[1];
        } else {
            const int a2 = wid - 4, oct = a2 >> 1, kh = a2 & 1;
            unsigned long long acc[16] = {0,0,0,0,0,0,0,0,0,0,0,0,0,0,0,0};
            uint32_t za = smb + (OFF_Z  + (256 + kh * 128 + ks) * ZSTR + bq * 4) * 4;
            uint32_t wa = smb + (OFF_W2 + (kh * 128 + ks) * W2STR + oct * 8) * 4;
            dot8r<16>(za, wa, 8 * ZSTR * 4, 8 * W2STR * 4, acc);
            kreduce8(acc, ks);
            int r = oct * 8 + ks;
            float* pb = smf + OFF_PB2 + kh * (48 * PBS) + r * PBS + bq * 4;
            *(unsigned long long*)(pb)     = acc[0];
            *(unsigned long long*)(pb + 2) = acc[1];
        }
        __syncthreads();

        // ---- xg = xv * sigmoid(A1x + A1h) -> g_xg ----
        if (tid < 256) {
            int rr = tid & 15, bb = tid >> 4;
            float s = smf[OFF_PB1H + rr * PBS + bb]
                    + smf[OFF_PB1H + 16 * PBS + rr * PBS + bb]
                    + smf[OFF_PB1X + rr * PBS + bb]
                    + smf[OFF_PB1X + 16 * PBS + rr * PBS + bb]
                    + smf[OFF_BA + rr];
            float a  = sigmoidf_(s);
            float xv = smf[OFF_XV + rr * XVS + bb];
            g_xg[(p * 16 + bb) * 256 + g * 16 + rr] = xv * a;
        }

        ++barn; pbar(base_sm, p, g, barn);   // xg published

        // ---- stage xg -> zT x-region ----
        for (int idx = tid; idx < 1024; idx += NTHR) {
            int bb = idx & 15, q4 = idx >> 4;
            float4 v = *(const float4*)&g_xg[(p * 16 + bb) * 256 + q4 * 4];
            int base = OFF_Z + (q4 * 4) * ZSTR + bb;
            smf[base] = v.x; smf[base + ZSTR] = v.y;
            smf[base + 2 * ZSTR] = v.z; smf[base + 3 * ZSTR] = v.w;
        }
        __syncthreads();

        // ==== C dot (warps 0-11) || A1x(t+1) (warps 12-15) ====
        if (wid < 12) {
            const int oct = wid >> 1, kh = wid & 1;
            unsigned long long acc[16] = {0,0,0,0,0,0,0,0,0,0,0,0,0,0,0,0};
            uint32_t za = smb + (OFF_Z  + (kh * 128 + ks) * ZSTR  + bq * 4) * 4;
            uint32_t wa = smb + (OFF_WC + (kh * 128 + ks) * WCSTR + oct * 8) * 4;
            dot8r<16>(za, wa, 8 * ZSTR * 4, 8 * WCSTR * 4, acc);
            kreduce8(acc, ks);
            int r = oct * 8 + ks;
            float* pb = smf + OFF_PBC + kh * (48 * PBS) + r * PBS + bq * 4;
            *(unsigned long long*)(pb)     = acc[0];
            *(unsigned long long*)(pb + 2) = acc[1];
        } else if (t + 1 < S_LEN) {
            const int a = wid - 12, oct = a >> 1, kh = a & 1;
            unsigned long long acc[16] = {0,0,0,0,0,0,0,0,0,0,0,0,0,0,0,0};
            uint32_t za = smb + (OFF_XN + (kh * 128 + ks) * ZSTR  + bq * 4) * 4;
            uint32_t wa = smb + (OFF_W1 + (kh * 128 + ks) * W1STR + oct * 8) * 4;
            dot8r<16>(za, wa, 8 * ZSTR * 4, 8 * W1STR * 4, acc);
            kreduce8(acc, ks);
            int r = oct * 8 + ks;
            float* pb = smf + OFF_PB1X + kh * (16 * PBS) + r * PBS + bq * 4;
            *(unsigned long long*)(pb)     = acc[0];
            *(unsigned long long*)(pb + 2) = acc[1];
        }
        __syncthreads();

        // ---- epilogue: gates + h update ----
        if (tid < 256) {
            int jj = tid & 15, bb = tid >> 4;
            int b  = p * 16 + bb;
            int j  = g * 16 + jj;
            float hp = smf[OFF_Z + (256 + j) * ZSTR + bb];
            float gi[3], gh_[3];
#pragma unroll
            for (int gate = 0; gate < 3; ++gate) {
                int r = gate * 16 + jj;
                gi[gate] = smf[OFF_PBC + r * PBS + bb]
                         + smf[OFF_PBC + 48 * PBS + r * PBS + bb]
                         + smf[OFF_BIH + r];
                gh_[gate] = smf[OFF_PB2 + r * PBS + bb]
                          + smf[OFF_PB2 + 48 * PBS + r * PBS + bb]
                          + smf[OFF_BHH + r];
            }
            float r_ = sigmoidf_(gi[0] + gh_[0]);
            float z_ = sigmoidf_(gi[1] + gh_[1]);
            float n_ = tanhf(gi[2] + r_ * gh_[2]);
            float hn = (1.0f - z_) * n_ + z_ * hp;
            g_h[b * 256 + j] = hn;
            out[(b * S_LEN + t) * 256 + j] = hn;
        }

        ++barn; pbar(base_sm, p, g, barn);   // h_new published
    }
}

extern "C" void kernel_launch(void* const* d_in, const int* in_sizes, int n_in,
                              void* d_out, int out_size) {
    const float* x     = (const float*)d_in[0];
    const float* hid   = (const float*)d_in[1];
    const float* W_att = (const float*)d_in[2];
    const float* b_att = (const float*)d_in[3];
    const float* w_ih  = (const float*)d_in[4];
    const float* b_ih  = (const float*)d_in[5];
    const float* w_hh  = (const float*)d_in[6];
    const float* b_hh  = (const float*)d_in[7];
    float* out = (float*)d_out;

    cudaFuncSetAttribute(gru_att_persistent,
                         cudaFuncAttributeMaxDynamicSharedMemorySize, SMEM_BYTES);

    gru_att_persistent<<<NBLK, NTHR, SMEM_BYTES>>>(
        x, hid, W_att, b_att, w_ih, b_ih, w_hh, b_hh, out);
}

// round 10
// speedup vs baseline: 1.3740x; 1.1203x over previous
#include <cuda_runtime.h>
#include <cstdint>

// ============================================================================
// GRU_Att_Layer R10: R9 + split-phase barrier overlap.
//  - bar A split into arrive -> stage XN=x(t+1) (overlap) -> wait
//  - xv buffer deleted: combine reads x(t) straight from XN (pre-overwrite)
//  - prologue = h staging only (shortest possible post-barrier chain)
//  - 8row x 4batch FFMA2 dot tiles, shfl k-reduce, conflict-free staging,
//    A1x(t+1) pipelined into C phase (warps 12-15)
// B=128,S=1024,I=256,H=256. 128 CTAs: g=blockIdx&15 rows, p=blockIdx>>4.
// 512 threads.
// ============================================================================

#define S_LEN 1024
#define NBLK  128
#define NTHR  512

#define ZSTR  20
#define W1STR 20
#define W2STR 52
#define WCSTR 52
#define PBS   18

// SMEM layout (float offsets)
#define OFF_W1   0                        // [512][20] W_att^T (16 rows)
#define OFF_W2   (OFF_W1 + 512*W1STR)     // 10240 [256][52] w_hh^T triples
#define OFF_WC   (OFF_W2 + 256*W2STR)     // 23552 [256][52] w_ih^T triples
#define OFF_Z    (OFF_WC + 256*WCSTR)     // 36864 [512][20]: [xg ; h]^T
#define OFF_XN   (OFF_Z  + 512*ZSTR)      // 47104 [256][20] x(t or t+1)^T
#define OFF_PB2  (OFF_XN + 256*ZSTR)      // 52224 [2][48][18] gh partials
#define OFF_PB1H (OFF_PB2 + 2*48*PBS)     // 53952 [2][16][18]
#define OFF_PB1X (OFF_PB1H + 2*16*PBS)    // 54528 [2][16][18]
#define OFF_PBC  (OFF_PB1X + 2*16*PBS)    // 55104 [2][48][18]
#define OFF_BA   (OFF_PBC + 2*48*PBS)     // 56832
#define OFF_BHH  (OFF_BA + 16)
#define OFF_BIH  (OFF_BHH + 48)
#define OFF_BASE (OFF_BIH + 48)           // 56944: 16 barrier bases
#define SMEM_FLOATS (OFF_BASE + 16)       // 56960
#define SMEM_BYTES  (SMEM_FLOATS * 4)     // 227840 B

// ---------------- scratch (device globals; allocation forbidden) -----------
__device__ __align__(16) float g_h [128 * 256];
__device__ __align__(16) float g_xg[128 * 256];
__device__ unsigned g_flag[NBLK * 32];

// ---------------- split flag barrier: arrive / wait -------------------------
__device__ __forceinline__ void pbar_arrive(const unsigned* base_sm, int g,
                                            unsigned n) {
    __syncthreads();                       // CTA's stores for this phase done
    if (threadIdx.x == 0) {
        __threadfence();                   // publish them
        *(volatile unsigned*)&g_flag[blockIdx.x * 32] = base_sm[g] + n;
    }
}
__device__ __forceinline__ void pbar_wait(const unsigned* base_sm, int p,
                                          unsigned n) {
    if (threadIdx.x < 16) {
        volatile unsigned* f = &g_flag[(p * 16 + threadIdx.x) * 32];
        unsigned tgt = base_sm[threadIdx.x] + n;
        while ((int)(*f - tgt) < 0) { }
        __threadfence();                   // acquire
    }
    __syncthreads();
}

__device__ __forceinline__ float sigmoidf_(float x) {
    return 1.0f / (1.0f + __expf(-x));
}
__device__ __forceinline__ uint32_t sm_u32(const void* ptr) {
    uint32_t a;
    asm("{ .reg .u64 t; cvta.to.shared.u64 t, %1; cvt.u32.u64 %0, t; }"
        : "=r"(a) : "l"(ptr));
    return a;
}
__device__ __forceinline__ unsigned long long dup2(float w) {
    unsigned long long d; uint32_t u = __float_as_uint(w);
    asm("mov.b64 %0, {%1,%1};" : "=l"(d) : "r"(u));
    return d;
}
#define FMA2(acc, a, b) \
    asm("fma.rn.f32x2 %0, %1, %2, %0;" : "+l"(acc) : "l"(a), "l"(b))
#define ADD2(d, s) \
    asm("add.rn.f32x2 %0, %0, %1;" : "+l"(d) : "l"(s))

// 8-row x 4-batch dot. lane=(ks=lane&7, bq=lane>>3).
template <int NITER>
__device__ __forceinline__ void dot8r(uint32_t za, uint32_t wa,
                                      int zstep, int wstep,
                                      unsigned long long acc[16]) {
#pragma unroll 4
    for (int i = 0; i < NITER; ++i) {
        unsigned long long z01, z23;
        asm volatile("ld.shared.v2.b64 {%0,%1}, [%2];"
                     : "=l"(z01), "=l"(z23) : "r"(za));
        float w0, w1, w2, w3, w4, w5, w6, w7;
        asm volatile("ld.shared.v4.f32 {%0,%1,%2,%3}, [%4];"
                     : "=f"(w0), "=f"(w1), "=f"(w2), "=f"(w3) : "r"(wa));
        asm volatile("ld.shared.v4.f32 {%0,%1,%2,%3}, [%4];"
                     : "=f"(w4), "=f"(w5), "=f"(w6), "=f"(w7) : "r"(wa + 16));
        unsigned long long d;
        d = dup2(w0); FMA2(acc[0],  d, z01); FMA2(acc[1],  d, z23);
        d = dup2(w1); FMA2(acc[2],  d, z01); FMA2(acc[3],  d, z23);
        d = dup2(w2); FMA2(acc[4],  d, z01); FMA2(acc[5],  d, z23);
        d = dup2(w3); FMA2(acc[6],  d, z01); FMA2(acc[7],  d, z23);
        d = dup2(w4); FMA2(acc[8],  d, z01); FMA2(acc[9],  d, z23);
        d = dup2(w5); FMA2(acc[10], d, z01); FMA2(acc[11], d, z23);
        d = dup2(w6); FMA2(acc[12], d, z01); FMA2(acc[13], d, z23);
        d = dup2(w7); FMA2(acc[14], d, z01); FMA2(acc[15], d, z23);
        za += zstep; wa += wstep;
    }
}

// shfl tree-reduce over ks (8 lanes): acc[0]=batches(bq*4+0,1),
// acc[1]=batches(bq*4+2,3) for local row == ks.
__device__ __forceinline__ void kreduce8(unsigned long long acc[16], int ks) {
    const bool h4 = (ks & 4) != 0;
#pragma unroll
    for (int r = 0; r < 4; ++r)
#pragma unroll
        for (int bp = 0; bp < 2; ++bp) {
            unsigned long long snd = h4 ? acc[r*2+bp] : acc[(r+4)*2+bp];
            unsigned long long kpt = h4 ? acc[(r+4)*2+bp] : acc[r*2+bp];
            unsigned long long rcv = __shfl_xor_sync(0xffffffffu, snd, 4);
            ADD2(kpt, rcv);
            acc[r*2+bp] = kpt;
        }
    const bool h2 = (ks & 2) != 0;
#pragma unroll
    for (int r = 0; r < 2; ++r)
#pragma unroll
        for (int bp = 0; bp < 2; ++bp) {
            unsigned long long snd = h2 ? acc[r*2+bp] : acc[(r+2)*2+bp];
            unsigned long long kpt = h2 ? acc[(r+2)*2+bp] : acc[r*2+bp];
            unsigned long long rcv = __shfl_xor_sync(0xffffffffu, snd, 2);
            ADD2(kpt, rcv);
            acc[r*2+bp] = kpt;
        }
    const bool h1 = (ks & 1) != 0;
#pragma unroll
    for (int bp = 0; bp < 2; ++bp) {
        unsigned long long snd = h1 ? acc[bp] : acc[2+bp];
        unsigned long long kpt = h1 ? acc[2+bp] : acc[bp];
        unsigned long long rcv = __shfl_xor_sync(0xffffffffu, snd, 1);
        ADD2(kpt, rcv);
        acc[bp] = kpt;
    }
}

__global__ void __launch_bounds__(NTHR, 1)
gru_att_persistent(const float* __restrict__ x,      // [B,S,I]
                   const float* __restrict__ hid,    // [B,H]
                   const float* __restrict__ W_att,  // [256,512]
                   const float* __restrict__ b_att,  // [256]
                   const float* __restrict__ w_ih,   // [768,256]
                   const float* __restrict__ b_ih,   // [768]
                   const float* __restrict__ w_hh,   // [768,256]
                   const float* __restrict__ b_hh,   // [768]
                   float* __restrict__ out)          // [B,S,H]
{
    extern __shared__ float smf[];
    const int tid  = threadIdx.x;
    const int g    = blockIdx.x & 15;
    const int p    = blockIdx.x >> 4;
    const int wid  = tid >> 5;
    const int lane = tid & 31;
    const int ks   = lane & 7;
    const int bq   = lane >> 3;
    const uint32_t smb = sm_u32(smf);
    unsigned* base_sm = (unsigned*)(smf + OFF_BASE);

    if (tid < 16) base_sm[tid] = g_flag[(p * 16 + tid) * 32];

    // ---- stage weights (transposed, gate-triple row sets) ----
    for (int idx = tid; idx < 512 * 16; idx += NTHR) {
        int k = idx >> 4, rr = idx & 15;
        smf[OFF_W1 + k * W1STR + rr] = W_att[(g * 16 + rr) * 512 + k];
    }
    for (int idx = tid; idx < 256 * 48; idx += NTHR) {
        int k = idx / 48, rl = idx % 48;
        int gate = rl >> 4, jj = rl & 15;
        smf[OFF_W2 + k * W2STR + rl] = w_hh[(gate * 256 + g * 16 + jj) * 256 + k];
    }
    for (int idx = tid; idx < 256 * 48; idx += NTHR) {
        int k = idx / 48, rl = idx % 48;
        int gate = rl >> 4, jj = rl & 15;
        smf[OFF_WC + k * WCSTR + rl] = w_ih[(gate * 256 + g * 16 + jj) * 256 + k];
    }
    if (tid < 16) smf[OFF_BA + tid] = b_att[g * 16 + tid];
    if (tid < 48) {
        int gate = tid >> 4, jj = tid & 15;
        smf[OFF_BHH + tid] = b_hh[gate * 256 + g * 16 + jj];
        smf[OFF_BIH + tid] = b_ih[gate * 256 + g * 16 + jj];
    }

    // ---- init hidden state (one writer block per batch group) ----
    if (g == 0) {
        for (int idx = tid; idx < 16 * 256; idx += NTHR) {
            int bb = idx >> 8, k = idx & 255;
            g_h[(p * 16 + bb) * 256 + k] = hid[(p * 16 + bb) * 256 + k];
        }
    }

    // ---- pre-loop: XN <- x(0); A1x(0) by warps 12-15 ----
    for (int idx = tid; idx < 1024; idx += NTHR) {
        int bb = idx & 15, q4 = idx >> 4;
        float4 v = *(const float4*)&x[((p * 16 + bb) * S_LEN + 0) * 256 + q4 * 4];
        int base = OFF_XN + (q4 * 4) * ZSTR + bb;
        smf[base] = v.x; smf[base + ZSTR] = v.y;
        smf[base + 2 * ZSTR] = v.z; smf[base + 3 * ZSTR] = v.w;
    }
    __syncthreads();
    if (wid >= 12) {
        const int a = wid - 12, oct = a >> 1, kh = a & 1;
        unsigned long long acc[16] = {0,0,0,0,0,0,0,0,0,0,0,0,0,0,0,0};
        uint32_t za = smb + (OFF_XN + (kh * 128 + ks) * ZSTR  + bq * 4) * 4;
        uint32_t wa = smb + (OFF_W1 + (kh * 128 + ks) * W1STR + oct * 8) * 4;
        dot8r<16>(za, wa, 8 * ZSTR * 4, 8 * W1STR * 4, acc);
        kreduce8(acc, ks);
        int r = oct * 8 + ks;
        float* pb = smf + OFF_PB1X + kh * (16 * PBS) + r * PBS + bq * 4;
        *(unsigned long long*)(pb)     = acc[0];
        *(unsigned long long*)(pb + 2) = acc[1];
    }

    unsigned barn = 1;
    pbar_arrive(base_sm, g, barn);
    pbar_wait(base_sm, p, barn);

    for (int t = 0; t < S_LEN; ++t) {
        // ==== prologue: ONLY h staging (shortest post-barrier chain) ====
        for (int idx = tid; idx < 1024; idx += NTHR) {
            int bb = idx & 15, q4 = idx >> 4;
            float4 v = *(const float4*)&g_h[(p * 16 + bb) * 256 + q4 * 4];
            int base = OFF_Z + (256 + q4 * 4) * ZSTR + bb;
            smf[base] = v.x; smf[base + ZSTR] = v.y;
            smf[base + 2 * ZSTR] = v.z; smf[base + 3 * ZSTR] = v.w;
        }
        __syncthreads();

        // ==== dot1 (balanced, K=256 each): A1h warps 0-3, A2 warps 4-15 ====
        if (wid < 4) {
            const int oct = wid >> 1, kh = wid & 1;
            unsigned long long acc[16] = {0,0,0,0,0,0,0,0,0,0,0,0,0,0,0,0};
            uint32_t za = smb + (OFF_Z  + (256 + kh * 128 + ks) * ZSTR + bq * 4) * 4;
            uint32_t wa = smb + (OFF_W1 + (256 + kh * 128 + ks) * W1STR + oct * 8) * 4;
            dot8r<16>(za, wa, 8 * ZSTR * 4, 8 * W1STR * 4, acc);
            kreduce8(acc, ks);
            int r = oct * 8 + ks;
            float* pb = smf + OFF_PB1H + kh * (16 * PBS) + r * PBS + bq * 4;
            *(unsigned long long*)(pb)     = acc[0];
            *(unsigned long long*)(pb + 2) = acc[1];
        } else {
            const int a2 = wid - 4, oct = a2 >> 1, kh = a2 & 1;
            unsigned long long acc[16] = {0,0,0,0,0,0,0,0,0,0,0,0,0,0,0,0};
            uint32_t za = smb + (OFF_Z  + (256 + kh * 128 + ks) * ZSTR + bq * 4) * 4;
            uint32_t wa = smb + (OFF_W2 + (kh * 128 + ks) * W2STR + oct * 8) * 4;
            dot8r<16>(za, wa, 8 * ZSTR * 4, 8 * W2STR * 4, acc);
            kreduce8(acc, ks);
            int r = oct * 8 + ks;
            float* pb = smf + OFF_PB2 + kh * (48 * PBS) + r * PBS + bq * 4;
            *(unsigned long long*)(pb)     = acc[0];
            *(unsigned long long*)(pb + 2) = acc[1];
        }
        __syncthreads();

        // ---- xg = x(t) * sigmoid(A1x + A1h); x(t) read from XN ----
        if (tid < 256) {
            int rr = tid & 15, bb = tid >> 4;
            float s = smf[OFF_PB1H + rr * PBS + bb]
                    + smf[OFF_PB1H + 16 * PBS + rr * PBS + bb]
                    + smf[OFF_PB1X + rr * PBS + bb]
                    + smf[OFF_PB1X + 16 * PBS + rr * PBS + bb]
                    + smf[OFF_BA + rr];
            float a  = sigmoidf_(s);
            float xv = smf[OFF_XN + (g * 16 + rr) * ZSTR + bb];   // x(t)
            g_xg[(p * 16 + bb) * 256 + g * 16 + rr] = xv * a;
        }

        // ==== bar A split: arrive, stage XN <- x(t+1) in the window, wait ====
        ++barn;
        pbar_arrive(base_sm, g, barn);       // (syncthreads inside: XN reads done)
        if (t + 1 < S_LEN) {
            for (int idx = tid; idx < 1024; idx += NTHR) {
                int bb = idx & 15, q4 = idx >> 4;
                float4 v = *(const float4*)
                    &x[((p * 16 + bb) * S_LEN + (t + 1)) * 256 + q4 * 4];
                int base = OFF_XN + (q4 * 4) * ZSTR + bb;
                smf[base] = v.x; smf[base + ZSTR] = v.y;
                smf[base + 2 * ZSTR] = v.z; smf[base + 3 * ZSTR] = v.w;
            }
        }
        pbar_wait(base_sm, p, barn);         // xg of all 16 CTAs visible

        // ---- stage xg -> zT x-region ----
        for (int idx = tid; idx < 1024; idx += NTHR) {
            int bb = idx & 15, q4 = idx >> 4;
            float4 v = *(const float4*)&g_xg[(p * 16 + bb) * 256 + q4 * 4];
            int base = OFF_Z + (q4 * 4) * ZSTR + bb;
            smf[base] = v.x; smf[base + ZSTR] = v.y;
            smf[base + 2 * ZSTR] = v.z; smf[base + 3 * ZSTR] = v.w;
        }
        __syncthreads();

        // ==== C dot (warps 0-11) || A1x(t+1) (warps 12-15, reads new XN) ====
        if (wid < 12) {
            const int oct = wid >> 1, kh = wid & 1;
            unsigned long long acc[16] = {0,0,0,0,0,0,0,0,0,0,0,0,0,0,0,0};
            uint32_t za = smb + (OFF_Z  + (kh * 128 + ks) * ZSTR  + bq * 4) * 4;
            uint32_t wa = smb + (OFF_WC + (kh * 128 + ks) * WCSTR + oct * 8) * 4;
            dot8r<16>(za, wa, 8 * ZSTR * 4, 8 * WCSTR * 4, acc);
            kreduce8(acc, ks);
            int r = oct * 8 + ks;
            float* pb = smf + OFF_PBC + kh * (48 * PBS) + r * PBS + bq * 4;
            *(unsigned long long*)(pb)     = acc[0];
            *(unsigned long long*)(pb + 2) = acc[1];
        } else if (t + 1 < S_LEN) {
            const int a = wid - 12, oct = a >> 1, kh = a & 1;
            unsigned long long acc[16] = {0,0,0,0,0,0,0,0,0,0,0,0,0,0,0,0};
            uint32_t za = smb + (OFF_XN + (kh * 128 + ks) * ZSTR  + bq * 4) * 4;
            uint32_t wa = smb + (OFF_W1 + (kh * 128 + ks) * W1STR + oct * 8) * 4;
            dot8r<16>(za, wa, 8 * ZSTR * 4, 8 * W1STR * 4, acc);
            kreduce8(acc, ks);
            int r = oct * 8 + ks;
            float* pb = smf + OFF_PB1X + kh * (16 * PBS) + r * PBS + bq * 4;
            *(unsigned long long*)(pb)     = acc[0];
            *(unsigned long long*)(pb + 2) = acc[1];
        }
        __syncthreads();

        // ---- epilogue: gates + h update ----
        if (tid < 256) {
            int jj = tid & 15, bb = tid >> 4;
            int b  = p * 16 + bb;
            int j  = g * 16 + jj;
            float hp = smf[OFF_Z + (256 + j) * ZSTR + bb];
            float gi[3], gh_[3];
#pragma unroll
            for (int gate = 0; gate < 3; ++gate) {
                int r = gate * 16 + jj;
                gi[gate] = smf[OFF_PBC + r * PBS + bb]
                         + smf[OFF_PBC + 48 * PBS + r * PBS + bb]
                         + smf[OFF_BIH + r];
                gh_[gate] = smf[OFF_PB2 + r * PBS + bb]
                          + smf[OFF_PB2 + 48 * PBS + r * PBS + bb]
                          + smf[OFF_BHH + r];
            }
            float r_ = sigmoidf_(gi[0] + gh_[0]);
            float z_ = sigmoidf_(gi[1] + gh_[1]);
            float n_ = tanhf(gi[2] + r_ * gh_[2]);
            float hn = (1.0f - z_) * n_ + z_ * hp;
            g_h[b * 256 + j] = hn;
            out[(b * S_LEN + t) * 256 + j] = hn;
        }

        // ==== bar B: h_new published (no independent work left to overlap) ====
        ++barn;
        pbar_arrive(base_sm, g, barn);
        pbar_wait(base_sm, p, barn);
    }
}

extern "C" void kernel_launch(void* const* d_in, const int* in_sizes, int n_in,
                              void* d_out, int out_size) {
    const float* x     = (const float*)d_in[0];
    const float* hid   = (const float*)d_in[1];
    const float* W_att = (const float*)d_in[2];
    const float* b_att = (const float*)d_in[3];
    const float* w_ih  = (const float*)d_in[4];
    const float* b_ih  = (const float*)d_in[5];
    const float* w_hh  = (const float*)d_in[6];
    const float* b_hh  = (const float*)d_in[7];
    float* out = (float*)d_out;

    cudaFuncSetAttribute(gru_att_persistent,
                         cudaFuncAttributeMaxDynamicSharedMemorySize, SMEM_BYTES);

    gru_att_persistent<<<NBLK, NTHR, SMEM_BYTES>>>(
        x, hid, W_att, b_att, w_ih, b_ih, w_hh, b_hh, out);
}

// round 11
// speedup vs baseline: 1.5536x; 1.1307x over previous
#include <cuda_runtime.h>
#include <cstdint>

// ============================================================================
// GRU_Att_Layer R11: R10 + decontended C phase and hidden epilogue I/O.
//  - A1x(t+1) moved from C phase into the bar-B spin window (warps 12-15)
//  - out STG moved into bar-B window (coalesced via zT re-read)
//  - transposed scratch g_hT/g_xgT [p][k][bb]: 128-bit stage ld/st, own-slice
//    skip (epilogue/combine STS own rows directly into zT)
//  - 8row x 4batch FFMA2 dot tiles, shfl k-reduce, split flag barriers
// B=128,S=1024,I=256,H=256. 128 CTAs: g=blockIdx&15 rows, p=blockIdx>>4.
// 512 threads.
// ============================================================================

#define S_LEN 1024
#define NBLK  128
#define NTHR  512

#define ZSTR  20
#define W1STR 20
#define W2STR 52
#define WCSTR 52
#define PBS   18

// SMEM layout (float offsets)
#define OFF_W1   0                        // [512][20] W_att^T (16 rows)
#define OFF_W2   (OFF_W1 + 512*W1STR)     // 10240 [256][52] w_hh^T triples
#define OFF_WC   (OFF_W2 + 256*W2STR)     // 23552 [256][52] w_ih^T triples
#define OFF_Z    (OFF_WC + 256*WCSTR)     // 36864 [512][20]: [xg ; h]^T
#define OFF_XN   (OFF_Z  + 512*ZSTR)      // 47104 [256][20] x(t or t+1)^T
#define OFF_PB2  (OFF_XN + 256*ZSTR)      // 52224 [2][48][18] gh partials
#define OFF_PB1H (OFF_PB2 + 2*48*PBS)     // 53952 [2][16][18]
#define OFF_PB1X (OFF_PB1H + 2*16*PBS)    // 54528 [2][16][18]
#define OFF_PBC  (OFF_PB1X + 2*16*PBS)    // 55104 [2][48][18]
#define OFF_BA   (OFF_PBC + 2*48*PBS)     // 56832
#define OFF_BHH  (OFF_BA + 16)
#define OFF_BIH  (OFF_BHH + 48)
#define OFF_BASE (OFF_BIH + 48)           // 56944: 16 barrier bases
#define SMEM_FLOATS (OFF_BASE + 16)       // 56960
#define SMEM_BYTES  (SMEM_FLOATS * 4)     // 227840 B

// ---------------- scratch (device globals; allocation forbidden) -----------
// transposed: [pgroup][k 0..255][bb 0..15]
__device__ __align__(16) float g_hT [8 * 256 * 16];
__device__ __align__(16) float g_xgT[8 * 256 * 16];
__device__ unsigned g_flag[NBLK * 32];

// ---------------- split flag barrier: arrive / wait -------------------------
__device__ __forceinline__ void pbar_arrive(const unsigned* base_sm, int g,
                                            unsigned n) {
    __syncthreads();                       // CTA's stores for this phase done
    if (threadIdx.x == 0) {
        __threadfence();                   // publish them
        *(volatile unsigned*)&g_flag[blockIdx.x * 32] = base_sm[g] + n;
    }
}
__device__ __forceinline__ void pbar_wait(const unsigned* base_sm, int p,
                                          unsigned n) {
    if (threadIdx.x < 16) {
        volatile unsigned* f = &g_flag[(p * 16 + threadIdx.x) * 32];
        unsigned tgt = base_sm[threadIdx.x] + n;
        while ((int)(*f - tgt) < 0) { }
        __threadfence();                   // acquire
    }
    __syncthreads();
}

__device__ __forceinline__ float sigmoidf_(float x) {
    return 1.0f / (1.0f + __expf(-x));
}
__device__ __forceinline__ uint32_t sm_u32(const void* ptr) {
    uint32_t a;
    asm("{ .reg .u64 t; cvta.to.shared.u64 t, %1; cvt.u32.u64 %0, t; }"
        : "=r"(a) : "l"(ptr));
    return a;
}
__device__ __forceinline__ unsigned long long dup2(float w) {
    unsigned long long d; uint32_t u = __float_as_uint(w);
    asm("mov.b64 %0, {%1,%1};" : "=l"(d) : "r"(u));
    return d;
}
#define FMA2(acc, a, b) \
    asm("fma.rn.f32x2 %0, %1, %2, %0;" : "+l"(acc) : "l"(a), "l"(b))
#define ADD2(d, s) \
    asm("add.rn.f32x2 %0, %0, %1;" : "+l"(d) : "l"(s))

// 8-row x 4-batch dot. lane=(ks=lane&7, bq=lane>>3).
template <int NITER>
__device__ __forceinline__ void dot8r(uint32_t za, uint32_t wa,
                                      int zstep, int wstep,
                                      unsigned long long acc[16]) {
#pragma unroll 4
    for (int i = 0; i < NITER; ++i) {
        unsigned long long z01, z23;
        asm volatile("ld.shared.v2.b64 {%0,%1}, [%2];"
                     : "=l"(z01), "=l"(z23) : "r"(za));
        float w0, w1, w2, w3, w4, w5, w6, w7;
        asm volatile("ld.shared.v4.f32 {%0,%1,%2,%3}, [%4];"
                     : "=f"(w0), "=f"(w1), "=f"(w2), "=f"(w3) : "r"(wa));
        asm volatile("ld.shared.v4.f32 {%0,%1,%2,%3}, [%4];"
                     : "=f"(w4), "=f"(w5), "=f"(w6), "=f"(w7) : "r"(wa + 16));
        unsigned long long d;
        d = dup2(w0); FMA2(acc[0],  d, z01); FMA2(acc[1],  d, z23);
        d = dup2(w1); FMA2(acc[2],  d, z01); FMA2(acc[3],  d, z23);
        d = dup2(w2); FMA2(acc[4],  d, z01); FMA2(acc[5],  d, z23);
        d = dup2(w3); FMA2(acc[6],  d, z01); FMA2(acc[7],  d, z23);
        d = dup2(w4); FMA2(acc[8],  d, z01); FMA2(acc[9],  d, z23);
        d = dup2(w5); FMA2(acc[10], d, z01); FMA2(acc[11], d, z23);
        d = dup2(w6); FMA2(acc[12], d, z01); FMA2(acc[13], d, z23);
        d = dup2(w7); FMA2(acc[14], d, z01); FMA2(acc[15], d, z23);
        za += zstep; wa += wstep;
    }
}

// shfl tree-reduce over ks (8 lanes): acc[0]=batches(bq*4+0,1),
// acc[1]=batches(bq*4+2,3) for local row == ks.
__device__ __forceinline__ void kreduce8(unsigned long long acc[16], int ks) {
    const bool h4 = (ks & 4) != 0;
#pragma unroll
    for (int r = 0; r < 4; ++r)
#pragma unroll
        for (int bp = 0; bp < 2; ++bp) {
            unsigned long long snd = h4 ? acc[r*2+bp] : acc[(r+4)*2+bp];
            unsigned long long kpt = h4 ? acc[(r+4)*2+bp] : acc[r*2+bp];
            unsigned long long rcv = __shfl_xor_sync(0xffffffffu, snd, 4);
            ADD2(kpt, rcv);
            acc[r*2+bp] = kpt;
        }
    const bool h2 = (ks & 2) != 0;
#pragma unroll
    for (int r = 0; r < 2; ++r)
#pragma unroll
        for (int bp = 0; bp < 2; ++bp) {
            unsigned long long snd = h2 ? acc[r*2+bp] : acc[(r+2)*2+bp];
            unsigned long long kpt = h2 ? acc[(r+2)*2+bp] : acc[r*2+bp];
            unsigned long long rcv = __shfl_xor_sync(0xffffffffu, snd, 2);
            ADD2(kpt, rcv);
            acc[r*2+bp] = kpt;
        }
    const bool h1 = (ks & 1) != 0;
#pragma unroll
    for (int bp = 0; bp < 2; ++bp) {
        unsigned long long snd = h1 ? acc[bp] : acc[2+bp];
        unsigned long long kpt = h1 ? acc[2+bp] : acc[bp];
        unsigned long long rcv = __shfl_xor_sync(0xffffffffu, snd, 1);
        ADD2(kpt, rcv);
        acc[bp] = kpt;
    }
}

__global__ void __launch_bounds__(NTHR, 1)
gru_att_persistent(const float* __restrict__ x,      // [B,S,I]
                   const float* __restrict__ hid,    // [B,H]
                   const float* __restrict__ W_att,  // [256,512]
                   const float* __restrict__ b_att,  // [256]
                   const float* __restrict__ w_ih,   // [768,256]
                   const float* __restrict__ b_ih,   // [768]
                   const float* __restrict__ w_hh,   // [768,256]
                   const float* __restrict__ b_hh,   // [768]
                   float* __restrict__ out)          // [B,S,H]
{
    extern __shared__ float smf[];
    const int tid  = threadIdx.x;
    const int g    = blockIdx.x & 15;
    const int p    = blockIdx.x >> 4;
    const int wid  = tid >> 5;
    const int lane = tid & 31;
    const int ks   = lane & 7;
    const int bq   = lane >> 3;
    const uint32_t smb = sm_u32(smf);
    unsigned* base_sm = (unsigned*)(smf + OFF_BASE);
    float* ghT  = g_hT  + p * 4096;   // [256][16]
    float* gxgT = g_xgT + p * 4096;

    if (tid < 16) base_sm[tid] = g_flag[(p * 16 + tid) * 32];

    // ---- stage weights (transposed, gate-triple row sets) ----
    for (int idx = tid; idx < 512 * 16; idx += NTHR) {
        int k = idx >> 4, rr = idx & 15;
        smf[OFF_W1 + k * W1STR + rr] = W_att[(g * 16 + rr) * 512 + k];
    }
    for (int idx = tid; idx < 256 * 48; idx += NTHR) {
        int k = idx / 48, rl = idx % 48;
        int gate = rl >> 4, jj = rl & 15;
        smf[OFF_W2 + k * W2STR + rl] = w_hh[(gate * 256 + g * 16 + jj) * 256 + k];
    }
    for (int idx = tid; idx < 256 * 48; idx += NTHR) {
        int k = idx / 48, rl = idx % 48;
        int gate = rl >> 4, jj = rl & 15;
        smf[OFF_WC + k * WCSTR + rl] = w_ih[(gate * 256 + g * 16 + jj) * 256 + k];
    }
    if (tid < 16) smf[OFF_BA + tid] = b_att[g * 16 + tid];
    if (tid < 48) {
        int gate = tid >> 4, jj = tid & 15;
        smf[OFF_BHH + tid] = b_hh[gate * 256 + g * 16 + jj];
        smf[OFF_BIH + tid] = b_ih[gate * 256 + g * 16 + jj];
    }

    // ---- init transposed hidden state (one writer block per batch group) ---
    if (g == 0) {
        for (int idx = tid; idx < 4096; idx += NTHR) {
            int k = idx >> 4, bb = idx & 15;
            ghT[idx] = hid[(p * 16 + bb) * 256 + k];
        }
    }
    // ---- own h-slice into zT (stage loops skip own rows forever after) ----
    if (tid < 256) {
        int bb = tid & 15, jj = tid >> 4;
        smf[OFF_Z + (256 + g * 16 + jj) * ZSTR + bb] =
            hid[(p * 16 + bb) * 256 + g * 16 + jj];
    }

    // ---- pre-loop: XN <- x(0); A1x(0) by warps 12-15 ----
    for (int idx = tid; idx < 1024; idx += NTHR) {
        int bb = idx & 15, q4 = idx >> 4;
        float4 v = *(const float4*)&x[((p * 16 + bb) * S_LEN + 0) * 256 + q4 * 4];
        int base = OFF_XN + (q4 * 4) * ZSTR + bb;
        smf[base] = v.x; smf[base + ZSTR] = v.y;
        smf[base + 2 * ZSTR] = v.z; smf[base + 3 * ZSTR] = v.w;
    }
    __syncthreads();
    if (wid >= 12) {
        const int a = wid - 12, oct = a >> 1, kh = a & 1;
        unsigned long long acc[16] = {0,0,0,0,0,0,0,0,0,0,0,0,0,0,0,0};
        uint32_t za = smb + (OFF_XN + (kh * 128 + ks) * ZSTR  + bq * 4) * 4;
        uint32_t wa = smb + (OFF_W1 + (kh * 128 + ks) * W1STR + oct * 8) * 4;
        dot8r<16>(za, wa, 8 * ZSTR * 4, 8 * W1STR * 4, acc);
        kreduce8(acc, ks);
        int r = oct * 8 + ks;
        float* pb = smf + OFF_PB1X + kh * (16 * PBS) + r * PBS + bq * 4;
        *(unsigned long long*)(pb)     = acc[0];
        *(unsigned long long*)(pb + 2) = acc[1];
    }

    unsigned barn = 1;
    pbar_arrive(base_sm, g, barn);
    pbar_wait(base_sm, p, barn);

    for (int t = 0; t < S_LEN; ++t) {
        // ==== prologue: stage peer h slices (128-bit ld/st, skip own) ====
        for (int idx = tid; idx < 1024; idx += NTHR) {
            int i = idx >> 2, bb4 = (idx & 3) << 2;
            if ((i >> 4) != g) {
                float4 v = *(const float4*)&ghT[i * 16 + bb4];
                *(float4*)&smf[OFF_Z + (256 + i) * ZSTR + bb4] = v;
            }
        }
        __syncthreads();

        // ==== dot1 (K=256 each): A1h warps 0-3, A2 warps 4-15 ====
        if (wid < 4) {
            const int oct = wid >> 1, kh = wid & 1;
            unsigned long long acc[16] = {0,0,0,0,0,0,0,0,0,0,0,0,0,0,0,0};
            uint32_t za = smb + (OFF_Z  + (256 + kh * 128 + ks) * ZSTR + bq * 4) * 4;
            uint32_t wa = smb + (OFF_W1 + (256 + kh * 128 + ks) * W1STR + oct * 8) * 4;
            dot8r<16>(za, wa, 8 * ZSTR * 4, 8 * W1STR * 4, acc);
            kreduce8(acc, ks);
            int r = oct * 8 + ks;
            float* pb = smf + OFF_PB1H + kh * (16 * PBS) + r * PBS + bq * 4;
            *(unsigned long long*)(pb)     = acc[0];
            *(unsigned long long*)(pb + 2) = acc[1];
        } else {
            const int a2 = wid - 4, oct = a2 >> 1, kh = a2 & 1;
            unsigned long long acc[16] = {0,0,0,0,0,0,0,0,0,0,0,0,0,0,0,0};
            uint32_t za = smb + (OFF_Z  + (256 + kh * 128 + ks) * ZSTR + bq * 4) * 4;
            uint32_t wa = smb + (OFF_W2 + (kh * 128 + ks) * W2STR + oct * 8) * 4;
            dot8r<16>(za, wa, 8 * ZSTR * 4, 8 * W2STR * 4, acc);
            kreduce8(acc, ks);
            int r = oct * 8 + ks;
            float* pb = smf + OFF_PB2 + kh * (48 * PBS) + r * PBS + bq * 4;
            *(unsigned long long*)(pb)     = acc[0];
            *(unsigned long long*)(pb + 2) = acc[1];
        }
        __syncthreads();

        // ---- xg = x(t)*sigmoid(A1x+A1h); STG transposed + STS own slice ----
        if (tid < 256) {
            int bb = tid & 15, rr = tid >> 4;
            float s = smf[OFF_PB1H + rr * PBS + bb]
                    + smf[OFF_PB1H + 16 * PBS + rr * PBS + bb]
                    + smf[OFF_PB1X + rr * PBS + bb]
                    + smf[OFF_PB1X + 16 * PBS + rr * PBS + bb]
                    + smf[OFF_BA + rr];
            float a  = sigmoidf_(s);
            float xv = smf[OFF_XN + (g * 16 + rr) * ZSTR + bb];   // x(t)
            float val = xv * a;
            gxgT[(g * 16 + rr) * 16 + bb] = val;                  // coalesced
            smf[OFF_Z + (g * 16 + rr) * ZSTR + bb] = val;         // own slice
        }

        // ==== bar A: arrive, stage XN <- x(t+1) in the window, wait ====
        ++barn;
        pbar_arrive(base_sm, g, barn);
        if (t + 1 < S_LEN) {
            for (int idx = tid; idx < 1024; idx += NTHR) {
                int bb = idx & 15, q4 = idx >> 4;
                float4 v = *(const float4*)
                    &x[((p * 16 + bb) * S_LEN + (t + 1)) * 256 + q4 * 4];
                int base = OFF_XN + (q4 * 4) * ZSTR + bb;
                smf[base] = v.x; smf[base + ZSTR] = v.y;
                smf[base + 2 * ZSTR] = v.z; smf[base + 3 * ZSTR] = v.w;
            }
        }
        pbar_wait(base_sm, p, barn);

        // ---- stage peer xg slices (skip own) ----
        for (int idx = tid; idx < 1024; idx += NTHR) {
            int i = idx >> 2, bb4 = (idx & 3) << 2;
            if ((i >> 4) != g) {
                float4 v = *(const float4*)&gxgT[i * 16 + bb4];
                *(float4*)&smf[OFF_Z + i * ZSTR + bb4] = v;
            }
        }
        __syncthreads();

        // ==== C dot: warps 0-11 only (warps 12-15 free -> clean SMSPs) ====
        if (wid < 12) {
            const int oct = wid >> 1, kh = wid & 1;
            unsigned long long acc[16] = {0,0,0,0,0,0,0,0,0,0,0,0,0,0,0,0};
            uint32_t za = smb + (OFF_Z  + (kh * 128 + ks) * ZSTR  + bq * 4) * 4;
            uint32_t wa = smb + (OFF_WC + (kh * 128 + ks) * WCSTR + oct * 8) * 4;
            dot8r<16>(za, wa, 8 * ZSTR * 4, 8 * WCSTR * 4, acc);
            kreduce8(acc, ks);
            int r = oct * 8 + ks;
            float* pb = smf + OFF_PBC + kh * (48 * PBS) + r * PBS + bq * 4;
            *(unsigned long long*)(pb)     = acc[0];
            *(unsigned long long*)(pb + 2) = acc[1];
        }
        __syncthreads();

        // ---- epilogue: gates + h update; STG g_hT coalesced + STS own zT ---
        if (tid < 256) {
            int bb = tid & 15, jj = tid >> 4;
            int j  = g * 16 + jj;
            float hp = smf[OFF_Z + (256 + j) * ZSTR + bb];
            float gi[3], gh_[3];
#pragma unroll
            for (int gate = 0; gate < 3; ++gate) {
                int r = gate * 16 + jj;
                gi[gate] = smf[OFF_PBC + r * PBS + bb]
                         + smf[OFF_PBC + 48 * PBS + r * PBS + bb]
                         + smf[OFF_BIH + r];
                gh_[gate] = smf[OFF_PB2 + r * PBS + bb]
                          + smf[OFF_PB2 + 48 * PBS + r * PBS + bb]
                          + smf[OFF_BHH + r];
            }
            float r_ = sigmoidf_(gi[0] + gh_[0]);
            float z_ = sigmoidf_(gi[1] + gh_[1]);
            float n_ = tanhf(gi[2] + r_ * gh_[2]);
            float hn = (1.0f - z_) * n_ + z_ * hp;
            ghT[j * 16 + bb] = hn;                        // coalesced STG
            smf[OFF_Z + (256 + j) * ZSTR + bb] = hn;      // own slice for t+1
        }

        // ==== bar B: arrive; window = out STG (warps 0-7) + A1x (12-15) ====
        ++barn;
        pbar_arrive(base_sm, g, barn);   // syncthreads: zT h-slice visible
        if (tid < 256) {                 // coalesced out write from zT
            int jj = tid & 15, bb = tid >> 4;
            float hv = smf[OFF_Z + (256 + g * 16 + jj) * ZSTR + bb];
            out[((p * 16 + bb) * S_LEN + t) * 256 + g * 16 + jj] = hv;
        } else if (wid >= 12 && t + 1 < S_LEN) {   // A1x(t+1) from XN
            const int a = wid - 12, oct = a >> 1, kh = a & 1;
            unsigned long long acc[16] = {0,0,0,0,0,0,0,0,0,0,0,0,0,0,0,0};
            uint32_t za = smb + (OFF_XN + (kh * 128 + ks) * ZSTR  + bq * 4) * 4;
            uint32_t wa = smb + (OFF_W1 + (kh * 128 + ks) * W1STR + oct * 8) * 4;
            dot8r<16>(za, wa, 8 * ZSTR * 4, 8 * W1STR * 4, acc);
            kreduce8(acc, ks);
            int r = oct * 8 + ks;
            float* pb = smf + OFF_PB1X + kh * (16 * PBS) + r * PBS + bq * 4;
            *(unsigned long long*)(pb)     = acc[0];
            *(unsigned long long*)(pb + 2) = acc[1];
        }
        pbar_wait(base_sm, p, barn);     // h_new of all 16 CTAs visible
    }
}

extern "C" void kernel_launch(void* const* d_in, const int* in_sizes, int n_in,
                              void* d_out, int out_size) {
    const float* x     = (const float*)d_in[0];
    const float* hid   = (const float*)d_in[1];
    const float* W_att = (const float*)d_in[2];
    const float* b_att = (const float*)d_in[3];
    const float* w_ih  = (const float*)d_in[4];
    const float* b_ih  = (const float*)d_in[5];
    const float* w_hh  = (const float*)d_in[6];
    const float* b_hh  = (const float*)d_in[7];
    float* out = (float*)d_out;

    cudaFuncSetAttribute(gru_att_persistent,
                         cudaFuncAttributeMaxDynamicSharedMemorySize, SMEM_BYTES);

    gru_att_persistent<<<NBLK, NTHR, SMEM_BYTES>>>(
        x, hid, W_att, b_att, w_ih, b_ih, w_hh, b_hh, out);
}